// round 2
// baseline (speedup 1.0000x reference)
#include <cuda_runtime.h>
#include <math.h>

// Fixed problem shapes
#define NN 50000
#define EE 800000
#define HH 8
#define CC 16
#define HC 128
#define FEdim 7
#define RH 500
#define SLOPE 0.01f
#define SCAN_B 1024
#define NBLK ((NN + SCAN_B - 1) / SCAN_B)   // 49

// ---------------- static device scratch ----------------
__device__ float g_q[NN * HC];
__device__ float g_k[NN * HC];
__device__ float g_v[NN * HC];
__device__ float g_skip[NN * HC];
__device__ float g_h[NN * HC];
__device__ float g_score[(size_t)EE * HH];
__device__ float g_r1[(size_t)NN * RH];
__device__ float g_r2[(size_t)NN * RH];
// CSR
__device__ int g_cnt[NN];
__device__ int g_scan[NN];
__device__ int g_rowptr[NN + 1];
__device__ int g_eid[EE];
__device__ int g_bsum[NBLK];

__device__ __forceinline__ float leaky(float v) { return v > 0.f ? v : SLOPE * v; }

// ================= CSR build =================
__global__ void csr_zero() {
    int i = blockIdx.x * blockDim.x + threadIdx.x;
    if (i < NN) g_cnt[i] = 0;
}
__global__ void csr_hist(const int* __restrict__ ei) {
    int i = blockIdx.x * blockDim.x + threadIdx.x;
    if (i < EE) atomicAdd(&g_cnt[ei[EE + i]], 1);
}
__global__ __launch_bounds__(SCAN_B) void csr_scan1() {
    __shared__ int s[SCAN_B];
    int t = threadIdx.x;
    int i = blockIdx.x * SCAN_B + t;
    int v = (i < NN) ? g_cnt[i] : 0;
    s[t] = v;
    __syncthreads();
    for (int off = 1; off < SCAN_B; off <<= 1) {
        int x = (t >= off) ? s[t - off] : 0;
        __syncthreads();
        s[t] += x;
        __syncthreads();
    }
    if (i < NN) g_scan[i] = s[t];
    if (t == SCAN_B - 1) g_bsum[blockIdx.x] = s[t];
}
__global__ void csr_scan2() {
    if (threadIdx.x == 0) {
        int run = 0;
        for (int b = 0; b < NBLK; b++) { int v = g_bsum[b]; g_bsum[b] = run; run += v; }
    }
}
__global__ void csr_scan3() {
    int i = blockIdx.x * blockDim.x + threadIdx.x;
    if (i < NN) {
        g_rowptr[i] = g_scan[i] - g_cnt[i] + g_bsum[i / SCAN_B];
        g_cnt[i] = 0;  // reuse as scatter cursor
    }
    if (i == 0) g_rowptr[NN] = EE;
}
__global__ void csr_scatter(const int* __restrict__ ei) {
    int e = blockIdx.x * blockDim.x + threadIdx.x;
    if (e >= EE) return;
    int d = ei[EE + e];
    int pos = g_rowptr[d] + atomicAdd(&g_cnt[d], 1);
    g_eid[pos] = e;
}

// ================= generic fp32 GEMM =================
#define BM 128
#define BN 128
#define BK 16
#define TM 8
#define TN 8

__device__ __forceinline__ void gemm_body(
    const float* __restrict__ A, const float* __restrict__ W,
    const float* __restrict__ bias, float* __restrict__ C,
    int M, int K, int Nn, int act, int bx, int by)
{
    __shared__ float As[BK][BM + 4];   // 528B row stride: 16B aligned for float4
    __shared__ float Bs[BK][BN];

    int tid = threadIdx.x;
    int tx = tid & 15;
    int ty = tid >> 4;
    int row0 = by * BM;
    int col0 = bx * BN;

    float acc[TM][TN];
#pragma unroll
    for (int i = 0; i < TM; i++)
#pragma unroll
        for (int j = 0; j < TN; j++) acc[i][j] = 0.f;

    for (int k0 = 0; k0 < K; k0 += BK) {
#pragma unroll
        for (int i = 0; i < 8; i++) {
            int idx = tid + i * 256;
            int kk = idx & 15;
            int m  = idx >> 4;
            int gr = row0 + m, gk = k0 + kk;
            As[kk][m] = (gr < M && gk < K) ? A[(size_t)gr * K + gk] : 0.f;
        }
#pragma unroll
        for (int i = 0; i < 8; i++) {
            int idx = tid + i * 256;
            int n  = idx & 127;
            int kk = idx >> 7;
            int gk = k0 + kk, gn = col0 + n;
            Bs[kk][n] = (gk < K && gn < Nn) ? W[(size_t)gk * Nn + gn] : 0.f;
        }
        __syncthreads();

#pragma unroll
        for (int kk = 0; kk < BK; kk++) {
            float4 a0 = *(const float4*)&As[kk][ty * TM];
            float4 a1 = *(const float4*)&As[kk][ty * TM + 4];
            float4 b0 = *(const float4*)&Bs[kk][tx * TN];
            float4 b1 = *(const float4*)&Bs[kk][tx * TN + 4];
            float a[TM] = {a0.x, a0.y, a0.z, a0.w, a1.x, a1.y, a1.z, a1.w};
            float b[TN] = {b0.x, b0.y, b0.z, b0.w, b1.x, b1.y, b1.z, b1.w};
#pragma unroll
            for (int i = 0; i < TM; i++)
#pragma unroll
                for (int j = 0; j < TN; j++)
                    acc[i][j] = fmaf(a[i], b[j], acc[i][j]);
        }
        __syncthreads();
    }

#pragma unroll
    for (int i = 0; i < TM; i++) {
        int gr = row0 + ty * TM + i;
        if (gr >= M) continue;
#pragma unroll
        for (int j = 0; j < TN; j++) {
            int gn = col0 + tx * TN + j;
            if (gn >= Nn) continue;
            float v = acc[i][j] + bias[gn];
            if (act) v = leaky(v);
            C[(size_t)gr * Nn + gn] = v;
        }
    }
}

__global__ __launch_bounds__(256) void gemm_bias_act(
    const float* __restrict__ A, const float* __restrict__ W,
    const float* __restrict__ bias, float* __restrict__ C,
    int M, int K, int Nn, int act)
{
    gemm_body(A, W, bias, C, M, K, Nn, act, blockIdx.x, blockIdx.y);
}

// Fused 4-way projection: z selects {q,k,v,skip}
__global__ __launch_bounds__(256) void gemm_qkvs(
    const float* __restrict__ A,
    const float* __restrict__ W0, const float* __restrict__ b0, float* __restrict__ C0,
    const float* __restrict__ W1, const float* __restrict__ b1, float* __restrict__ C1,
    const float* __restrict__ W2, const float* __restrict__ b2, float* __restrict__ C2,
    const float* __restrict__ W3, const float* __restrict__ b3, float* __restrict__ C3)
{
    const float* W; const float* b; float* C;
    switch (blockIdx.z) {
        case 0: W = W0; b = b0; C = C0; break;
        case 1: W = W1; b = b1; C = C1; break;
        case 2: W = W2; b = b2; C = C2; break;
        default: W = W3; b = b3; C = C3; break;
    }
    gemm_body(A, W, b, C, NN, HC, HC, 0, blockIdx.x, blockIdx.y);
}

// ================= layer-1 projections (K = 2) =================
__global__ void proj_first(const float* __restrict__ x,
    const float* __restrict__ Wq, const float* __restrict__ bq,
    const float* __restrict__ Wk, const float* __restrict__ bk,
    const float* __restrict__ Wv, const float* __restrict__ bv,
    const float* __restrict__ Ws, const float* __restrict__ bs)
{
    int idx = blockIdx.x * blockDim.x + threadIdx.x;
    if (idx >= NN * HC) return;
    int n = idx >> 7, c = idx & 127;
    float x0 = x[n * 2], x1 = x[n * 2 + 1];
    g_q[idx]    = fmaf(x0, __ldg(Wq + c), fmaf(x1, __ldg(Wq + HC + c), __ldg(bq + c)));
    g_k[idx]    = fmaf(x0, __ldg(Wk + c), fmaf(x1, __ldg(Wk + HC + c), __ldg(bk + c)));
    g_v[idx]    = fmaf(x0, __ldg(Wv + c), fmaf(x1, __ldg(Wv + HC + c), __ldg(bv + c)));
    g_skip[idx] = fmaf(x0, __ldg(Ws + c), fmaf(x1, __ldg(Ws + HC + c), __ldg(bs + c)));
}

// ================= edge scores (warp per edge) =================
__global__ __launch_bounds__(256) void edge_score_kernel(
    const int* __restrict__ ei, const float* __restrict__ ea,
    const float* __restrict__ We, const float* __restrict__ be)
{
    int gw = (int)((blockIdx.x * (size_t)blockDim.x + threadIdx.x) >> 5);
    int lane = threadIdx.x & 31;
    if (gw >= EE) return;
    int src = ei[gw];
    int dst = ei[EE + gw];
    int c0 = lane * 4;

    float4 q4 = *(const float4*)(g_q + (size_t)dst * HC + c0);
    float4 k4 = *(const float4*)(g_k + (size_t)src * HC + c0);

    float e0 = __ldg(be + c0), e1 = __ldg(be + c0 + 1);
    float e2 = __ldg(be + c0 + 2), e3 = __ldg(be + c0 + 3);
#pragma unroll
    for (int f = 0; f < FEdim; f++) {
        float af = __ldg(ea + (size_t)gw * FEdim + f);
        const float* w = We + f * HC + c0;
        e0 = fmaf(af, __ldg(w + 0), e0);
        e1 = fmaf(af, __ldg(w + 1), e1);
        e2 = fmaf(af, __ldg(w + 2), e2);
        e3 = fmaf(af, __ldg(w + 3), e3);
    }

    float s = q4.x * (k4.x + e0) + q4.y * (k4.y + e1)
            + q4.z * (k4.z + e2) + q4.w * (k4.w + e3);
    s += __shfl_xor_sync(0xffffffffu, s, 1);
    s += __shfl_xor_sync(0xffffffffu, s, 2);

    if ((lane & 3) == 0)
        g_score[(size_t)gw * HH + (lane >> 2)] = s * 0.25f;   // 1/sqrt(16)
}

// ================= per-dst aggregation (warp per node, no atomics) =========
__global__ __launch_bounds__(256) void dst_aggregate(
    const int* __restrict__ ei, const float* __restrict__ ea,
    const float* __restrict__ We, const float* __restrict__ be)
{
    int node = (int)((blockIdx.x * (size_t)blockDim.x + threadIdx.x) >> 5);
    int lane = threadIdx.x & 31;
    if (node >= NN) return;
    int c0 = lane * 4;
    int h = lane >> 2;

    // hoist edge-invariant weights into registers
    float w0[FEdim], w1[FEdim], w2[FEdim], w3[FEdim];
#pragma unroll
    for (int f = 0; f < FEdim; f++) {
        const float* w = We + f * HC + c0;
        w0[f] = __ldg(w + 0); w1[f] = __ldg(w + 1);
        w2[f] = __ldg(w + 2); w3[f] = __ldg(w + 3);
    }
    float be0 = __ldg(be + c0),     be1 = __ldg(be + c0 + 1);
    float be2 = __ldg(be + c0 + 2), be3 = __ldg(be + c0 + 3);

    int beg = g_rowptr[node], end = g_rowptr[node + 1];

    // pass 1: per-head max
    float mx = -__int_as_float(0x7f800000);  // -inf
    for (int i = beg; i < end; i++) {
        int e = g_eid[i];
        mx = fmaxf(mx, g_score[(size_t)e * HH + h]);
    }

    // pass 2: exp-weighted accumulation
    float a0 = 0.f, a1 = 0.f, a2 = 0.f, a3 = 0.f, den = 0.f;
    for (int i = beg; i < end; i++) {
        int e = g_eid[i];
        int src = ei[e];
        float ex = __expf(g_score[(size_t)e * HH + h] - mx);
        float4 v4 = *(const float4*)(g_v + (size_t)src * HC + c0);
        float e0 = be0, e1 = be1, e2 = be2, e3 = be3;
#pragma unroll
        for (int f = 0; f < FEdim; f++) {
            float af = __ldg(ea + (size_t)e * FEdim + f);
            e0 = fmaf(af, w0[f], e0);
            e1 = fmaf(af, w1[f], e1);
            e2 = fmaf(af, w2[f], e2);
            e3 = fmaf(af, w3[f], e3);
        }
        a0 = fmaf(ex, v4.x + e0, a0);
        a1 = fmaf(ex, v4.y + e1, a1);
        a2 = fmaf(ex, v4.z + e2, a2);
        a3 = fmaf(ex, v4.w + e3, a3);
        den += ex;
    }

    float inv = (den > 0.f) ? 1.f / den : 0.f;
    size_t idx = (size_t)node * HC + c0;
    g_h[idx + 0] = leaky(g_skip[idx + 0] + a0 * inv);
    g_h[idx + 1] = leaky(g_skip[idx + 1] + a1 * inv);
    g_h[idx + 2] = leaky(g_skip[idx + 2] + a2 * inv);
    g_h[idx + 3] = leaky(g_skip[idx + 3] + a3 * inv);
}

// ================= final dot =================
__global__ void final_dot_kernel(const float* __restrict__ w,
                                 const float* __restrict__ b,
                                 float* __restrict__ out)
{
    int gw = (int)((blockIdx.x * (size_t)blockDim.x + threadIdx.x) >> 5);
    int lane = threadIdx.x & 31;
    if (gw >= NN) return;
    const float* row = g_r2 + (size_t)gw * RH;
    float s = 0.f;
    for (int k = lane; k < RH; k += 32) s = fmaf(row[k], __ldg(w + k), s);
#pragma unroll
    for (int o = 16; o; o >>= 1) s += __shfl_xor_sync(0xffffffffu, s, o);
    if (lane == 0) out[gw] = s + __ldg(b);
}

// ================= host orchestration =================
extern "C" void kernel_launch(void* const* d_in, const int* in_sizes, int n_in,
                              void* d_out, int out_size)
{
    const float* x   = (const float*)d_in[0];
    const int*   ei  = (const int*)  d_in[1];
    const float* ea  = (const float*)d_in[2];
    const float* Wq1 = (const float*)d_in[3];
    const float* bq1 = (const float*)d_in[4];
    const float* Wk1 = (const float*)d_in[5];
    const float* bk1 = (const float*)d_in[6];
    const float* Wv1 = (const float*)d_in[7];
    const float* bv1 = (const float*)d_in[8];
    const float* We1 = (const float*)d_in[9];
    const float* be1 = (const float*)d_in[10];
    const float* Ws1 = (const float*)d_in[11];
    const float* bs1 = (const float*)d_in[12];
    const float* Wqr = (const float*)d_in[13];
    const float* bqr = (const float*)d_in[14];
    const float* Wkr = (const float*)d_in[15];
    const float* bkr = (const float*)d_in[16];
    const float* Wvr = (const float*)d_in[17];
    const float* bvr = (const float*)d_in[18];
    const float* Wer = (const float*)d_in[19];
    const float* ber = (const float*)d_in[20];
    const float* Wsr = (const float*)d_in[21];
    const float* bsr = (const float*)d_in[22];
    const float* Wr1 = (const float*)d_in[23];
    const float* br1 = (const float*)d_in[24];
    const float* Wrm = (const float*)d_in[25];
    const float* brm = (const float*)d_in[26];
    const float* Wre = (const float*)d_in[27];
    const float* bre = (const float*)d_in[28];
    float* out = (float*)d_out;

    float *pq, *pk, *pv, *pskip, *ph, *pr1, *pr2;
    cudaGetSymbolAddress((void**)&pq,    g_q);
    cudaGetSymbolAddress((void**)&pk,    g_k);
    cudaGetSymbolAddress((void**)&pv,    g_v);
    cudaGetSymbolAddress((void**)&pskip, g_skip);
    cudaGetSymbolAddress((void**)&ph,    g_h);
    cudaGetSymbolAddress((void**)&pr1,   g_r1);
    cudaGetSymbolAddress((void**)&pr2,   g_r2);

    const int nodeBlocks  = (NN * HC + 255) / 256;
    const int edgeBlocks  = (EE + 255) / 256;
    const int edgeWBlocks = (int)(((size_t)EE * 32 + 255) / 256);
    const int nodeWBlocks = (int)(((size_t)NN * 32 + 255) / 256);

    // ---- CSR build (once; reused by all 4 layers) ----
    csr_zero<<<(NN + 255) / 256, 256>>>();
    csr_hist<<<edgeBlocks, 256>>>(ei);
    csr_scan1<<<NBLK, SCAN_B>>>();
    csr_scan2<<<1, 32>>>();
    csr_scan3<<<(NN + 255) / 256, 256>>>();
    csr_scatter<<<edgeBlocks, 256>>>(ei);

    // ---- layer 1 (input dim = 2) ----
    proj_first<<<nodeBlocks, 256>>>(x, Wq1, bq1, Wk1, bk1, Wv1, bv1, Ws1, bs1);
    edge_score_kernel<<<edgeWBlocks, 256>>>(ei, ea, We1, be1);
    dst_aggregate<<<nodeWBlocks, 256>>>(ei, ea, We1, be1);

    // ---- layers 2..4 (input dim = 128) ----
    dim3 gQKV(1, (NN + BM - 1) / BM, 4);
    for (int i = 0; i < 3; i++) {
        const float* Wq = Wqr + (size_t)i * HC * HC;  const float* bq = bqr + i * HC;
        const float* Wk = Wkr + (size_t)i * HC * HC;  const float* bk = bkr + i * HC;
        const float* Wv = Wvr + (size_t)i * HC * HC;  const float* bv = bvr + i * HC;
        const float* We = Wer + (size_t)i * FEdim * HC; const float* be = ber + i * HC;
        const float* Ws = Wsr + (size_t)i * HC * HC;  const float* bs = bsr + i * HC;

        gemm_qkvs<<<gQKV, 256>>>(ph, Wq, bq, pq, Wk, bk, pk, Wv, bv, pv, Ws, bs, pskip);
        edge_score_kernel<<<edgeWBlocks, 256>>>(ei, ea, We, be);
        dst_aggregate<<<nodeWBlocks, 256>>>(ei, ea, We, be);
    }

    // ---- regression head ----
    dim3 gH1((RH + BN - 1) / BN, (NN + BM - 1) / BM);
    gemm_bias_act<<<gH1, 256>>>(ph,  Wr1, br1, pr1, NN, HC, RH, 1);
    gemm_bias_act<<<gH1, 256>>>(pr1, Wrm, brm, pr2, NN, RH, RH, 1);
    final_dot_kernel<<<nodeWBlocks, 256>>>(Wre, bre, out);
}

// round 4
// speedup vs baseline: 1.1084x; 1.1084x over previous
#include <cuda_runtime.h>
#include <math.h>

// Fixed problem shapes
#define NN 50000
#define EE 800000
#define HH 8
#define CC 16
#define HC 128
#define FEdim 7
#define RH 500
#define SLOPE 0.01f
#define SCAN_B 1024
#define NBLK ((NN + SCAN_B - 1) / SCAN_B)   // 49

// ---------------- static device scratch ----------------
__device__ float g_q[NN * HC];
__device__ float g_k[NN * HC];
__device__ float g_v[NN * HC];
__device__ float g_skip[NN * HC];
__device__ float g_h[NN * HC];
__device__ float g_t[(size_t)NN * 64];          // per-node q-projected edge weights (8 heads x 8)
__device__ float g_r1[(size_t)NN * RH];
// CSR (built once, reused by all 4 layers)
__device__ int   g_cnt[NN];
__device__ int   g_scan[NN];
__device__ int   g_rowptr[NN + 1];
__device__ int   g_src_s[EE];                   // src node per sorted edge
__device__ float g_ea_s[(size_t)EE * 8];        // sorted edge attrs, padded, [7]=1.0
__device__ int   g_bsum[NBLK];

__device__ __forceinline__ float leaky(float v) { return v > 0.f ? v : SLOPE * v; }

// ================= CSR build =================
__global__ void csr_zero() {
    int i = blockIdx.x * blockDim.x + threadIdx.x;
    if (i < NN) g_cnt[i] = 0;
}
__global__ void csr_hist(const int* __restrict__ ei) {
    int i = blockIdx.x * blockDim.x + threadIdx.x;
    if (i < EE) atomicAdd(&g_cnt[ei[EE + i]], 1);
}
__global__ __launch_bounds__(SCAN_B) void csr_scan1() {
    __shared__ int s[SCAN_B];
    int t = threadIdx.x;
    int i = blockIdx.x * SCAN_B + t;
    int v = (i < NN) ? g_cnt[i] : 0;
    s[t] = v;
    __syncthreads();
    for (int off = 1; off < SCAN_B; off <<= 1) {
        int x = (t >= off) ? s[t - off] : 0;
        __syncthreads();
        s[t] += x;
        __syncthreads();
    }
    if (i < NN) g_scan[i] = s[t];
    if (t == SCAN_B - 1) g_bsum[blockIdx.x] = s[t];
}
__global__ void csr_scan2() {
    if (threadIdx.x == 0) {
        int run = 0;
        for (int b = 0; b < NBLK; b++) { int v = g_bsum[b]; g_bsum[b] = run; run += v; }
    }
}
__global__ void csr_scan3() {
    int i = blockIdx.x * blockDim.x + threadIdx.x;
    if (i < NN) {
        g_rowptr[i] = g_scan[i] - g_cnt[i] + g_bsum[i / SCAN_B];
        g_cnt[i] = 0;  // reuse as scatter cursor
    }
    if (i == 0) g_rowptr[NN] = EE;
}
__global__ void csr_scatter(const int* __restrict__ ei, const float* __restrict__ ea) {
    int e = blockIdx.x * blockDim.x + threadIdx.x;
    if (e >= EE) return;
    int d = ei[EE + e];
    int pos = g_rowptr[d] + atomicAdd(&g_cnt[d], 1);
    g_src_s[pos] = ei[e];
    const float* a = ea + (size_t)e * FEdim;
    float* o = g_ea_s + (size_t)pos * 8;
    o[0] = a[0]; o[1] = a[1]; o[2] = a[2]; o[3] = a[3];
    o[4] = a[4]; o[5] = a[5]; o[6] = a[6]; o[7] = 1.0f;   // pad = 1 folds bias via t[7]
}

// ================= generic fp32 GEMM =================
#define BM 128
#define BN 128
#define BK 16
#define TM 8
#define TN 8

// Loads tiles + accumulates; epilogue left to caller. acc indexed [row][col].
__device__ __forceinline__ void gemm_accum(
    const float* __restrict__ A, const float* __restrict__ W,
    int M, int K, int Nn, int bx, int by,
    float (&acc)[TM][TN],
    float (*As)[BM + 4], float (*Bs)[BN])
{
    int tid = threadIdx.x;
    int row0 = by * BM;
    int col0 = bx * BN;
    int tx = tid & 15;
    int ty = tid >> 4;

    for (int k0 = 0; k0 < K; k0 += BK) {
#pragma unroll
        for (int i = 0; i < 8; i++) {
            int idx = tid + i * 256;
            int kk = idx & 15;
            int m  = idx >> 4;
            int gr = row0 + m, gk = k0 + kk;
            As[kk][m] = (gr < M && gk < K) ? A[(size_t)gr * K + gk] : 0.f;
        }
#pragma unroll
        for (int i = 0; i < 8; i++) {
            int idx = tid + i * 256;
            int n  = idx & 127;
            int kk = idx >> 7;
            int gk = k0 + kk, gn = col0 + n;
            Bs[kk][n] = (gk < K && gn < Nn) ? W[(size_t)gk * Nn + gn] : 0.f;
        }
        __syncthreads();

#pragma unroll
        for (int kk = 0; kk < BK; kk++) {
            float4 a0 = *(const float4*)&As[kk][ty * TM];
            float4 a1 = *(const float4*)&As[kk][ty * TM + 4];
            float4 b0 = *(const float4*)&Bs[kk][tx * TN];
            float4 b1 = *(const float4*)&Bs[kk][tx * TN + 4];
            float a[TM] = {a0.x, a0.y, a0.z, a0.w, a1.x, a1.y, a1.z, a1.w};
            float b[TN] = {b0.x, b0.y, b0.z, b0.w, b1.x, b1.y, b1.z, b1.w};
#pragma unroll
            for (int i = 0; i < TM; i++)
#pragma unroll
                for (int j = 0; j < TN; j++)
                    acc[i][j] = fmaf(a[i], b[j], acc[i][j]);
        }
        __syncthreads();
    }
}

__global__ __launch_bounds__(256) void gemm_bias_act(
    const float* __restrict__ A, const float* __restrict__ W,
    const float* __restrict__ bias, float* __restrict__ C,
    int M, int K, int Nn, int act)
{
    __shared__ float As[BK][BM + 4];
    __shared__ float Bs[BK][BN];
    float acc[TM][TN];
#pragma unroll
    for (int i = 0; i < TM; i++)
#pragma unroll
        for (int j = 0; j < TN; j++) acc[i][j] = 0.f;

    gemm_accum(A, W, M, K, Nn, blockIdx.x, blockIdx.y, acc, As, Bs);

    int tid = threadIdx.x;
    int tx = tid & 15, ty = tid >> 4;
    int row0 = blockIdx.y * BM, col0 = blockIdx.x * BN;
#pragma unroll
    for (int i = 0; i < TM; i++) {
        int gr = row0 + ty * TM + i;
        if (gr >= M) continue;
#pragma unroll
        for (int j = 0; j < TN; j++) {
            int gn = col0 + tx * TN + j;
            if (gn >= Nn) continue;
            float v = acc[i][j] + bias[gn];
            if (act) v = leaky(v);
            C[(size_t)gr * Nn + gn] = v;
        }
    }
}

// Fused 4-way projection: z selects {q,k,v,skip}
__global__ __launch_bounds__(256) void gemm_qkvs(
    const float* __restrict__ A,
    const float* __restrict__ W0, const float* __restrict__ b0, float* __restrict__ C0,
    const float* __restrict__ W1, const float* __restrict__ b1, float* __restrict__ C1,
    const float* __restrict__ W2, const float* __restrict__ b2, float* __restrict__ C2,
    const float* __restrict__ W3, const float* __restrict__ b3, float* __restrict__ C3)
{
    const float* W; const float* b; float* C;
    switch (blockIdx.z) {
        case 0: W = W0; b = b0; C = C0; break;
        case 1: W = W1; b = b1; C = C1; break;
        case 2: W = W2; b = b2; C = C2; break;
        default: W = W3; b = b3; C = C3; break;
    }
    __shared__ float As[BK][BM + 4];
    __shared__ float Bs[BK][BN];
    float acc[TM][TN];
#pragma unroll
    for (int i = 0; i < TM; i++)
#pragma unroll
        for (int j = 0; j < TN; j++) acc[i][j] = 0.f;

    gemm_accum(A, W, NN, HC, HC, blockIdx.x, blockIdx.y, acc, As, Bs);

    int tid = threadIdx.x;
    int tx = tid & 15, ty = tid >> 4;
    int row0 = blockIdx.y * BM, col0 = blockIdx.x * BN;
#pragma unroll
    for (int i = 0; i < TM; i++) {
        int gr = row0 + ty * TM + i;
        if (gr >= NN) continue;
#pragma unroll
        for (int j = 0; j < TN; j++) {
            int gn = col0 + tx * TN + j;
            C[(size_t)gr * HC + gn] = acc[i][j] + b[gn];
        }
    }
}

// Fused tail: out[r] += sum_n leaky(r1[r,:]@Wrm[:,n] + brm[n]) * Wre[n]
__global__ __launch_bounds__(256) void gemm_head_tail(
    const float* __restrict__ A, const float* __restrict__ W,
    const float* __restrict__ bias, const float* __restrict__ wre,
    float* __restrict__ out)
{
    __shared__ float As[BK][BM + 4];
    __shared__ float Bs[BK][BN];
    float acc[TM][TN];
#pragma unroll
    for (int i = 0; i < TM; i++)
#pragma unroll
        for (int j = 0; j < TN; j++) acc[i][j] = 0.f;

    gemm_accum(A, W, NN, RH, RH, blockIdx.x, blockIdx.y, acc, As, Bs);

    int tid = threadIdx.x;
    int tx = tid & 15, ty = tid >> 4;
    int row0 = blockIdx.y * BM, col0 = blockIdx.x * BN;

    float wr[TN], bi[TN];
#pragma unroll
    for (int j = 0; j < TN; j++) {
        int gn = col0 + tx * TN + j;
        wr[j] = (gn < RH) ? __ldg(wre + gn)  : 0.f;
        bi[j] = (gn < RH) ? __ldg(bias + gn) : 0.f;
    }

#pragma unroll
    for (int i = 0; i < TM; i++) {
        int gr = row0 + ty * TM + i;
        float p = 0.f;
#pragma unroll
        for (int j = 0; j < TN; j++)
            p = fmaf(leaky(acc[i][j] + bi[j]), wr[j], p);
        // reduce across the 16 tx lanes (same ty) — xor offsets stay in 16-lane half
        p += __shfl_xor_sync(0xffffffffu, p, 1);
        p += __shfl_xor_sync(0xffffffffu, p, 2);
        p += __shfl_xor_sync(0xffffffffu, p, 4);
        p += __shfl_xor_sync(0xffffffffu, p, 8);
        if (tx == 0 && gr < NN) atomicAdd(out + gr, p);
    }
}

__global__ void out_init(const float* __restrict__ bre, float* __restrict__ out)
{
    int i = blockIdx.x * blockDim.x + threadIdx.x;
    if (i < NN) out[i] = __ldg(bre);
}

// ================= layer-1 projections (K = 2) =================
__global__ void proj_first(const float* __restrict__ x,
    const float* __restrict__ Wq, const float* __restrict__ bq,
    const float* __restrict__ Wk, const float* __restrict__ bk,
    const float* __restrict__ Wv, const float* __restrict__ bv,
    const float* __restrict__ Ws, const float* __restrict__ bs)
{
    int idx = blockIdx.x * blockDim.x + threadIdx.x;
    if (idx >= NN * HC) return;
    int n = idx >> 7, c = idx & 127;
    float x0 = x[n * 2], x1 = x[n * 2 + 1];
    g_q[idx]    = fmaf(x0, __ldg(Wq + c), fmaf(x1, __ldg(Wq + HC + c), __ldg(bq + c)));
    g_k[idx]    = fmaf(x0, __ldg(Wk + c), fmaf(x1, __ldg(Wk + HC + c), __ldg(bk + c)));
    g_v[idx]    = fmaf(x0, __ldg(Wv + c), fmaf(x1, __ldg(Wv + HC + c), __ldg(bv + c)));
    g_skip[idx] = fmaf(x0, __ldg(Ws + c), fmaf(x1, __ldg(Ws + HC + c), __ldg(bs + c)));
}

// ============ t = per-(node,head) projection of q through We/be ============
// t[n,h,f] = sum_c q[n,h*16+c] * We[f, h*16+c]   (f=7 slot uses be)
__global__ void t_compute(const float* __restrict__ We, const float* __restrict__ be)
{
    int idx = blockIdx.x * blockDim.x + threadIdx.x;   // n*64 + h*8 + f
    if (idx >= NN * 64) return;
    int f = idx & 7;
    int h = (idx >> 3) & 7;
    int n = idx >> 6;
    const float* w = (f < 7) ? (We + f * HC + h * 16) : (be + h * 16);
    const float* q = g_q + (size_t)n * HC + h * 16;
    float s = 0.f;
#pragma unroll
    for (int c = 0; c < 16; c++) s = fmaf(q[c], __ldg(w + c), s);
    g_t[idx] = s;
}

// ============ fused edge pass: online softmax + aggregation ============
// 4 warps per node; lane owns one channel c; warp covers 2 heads.
__global__ __launch_bounds__(256) void fused_aggregate(
    const float* __restrict__ We, const float* __restrict__ be)
{
    int gw = (int)((blockIdx.x * (size_t)blockDim.x + threadIdx.x) >> 5);
    int lane = threadIdx.x & 31;
    int node = gw >> 2;
    int qt = gw & 3;
    if (node >= NN) return;
    int c = qt * 32 + lane;
    int h = c >> 4;

    float qv = g_q[(size_t)node * HC + c];
    const float* tp = g_t + (size_t)node * 64 + h * 8;
    float t0 = tp[0], t1 = tp[1], t2 = tp[2], t3 = tp[3];
    float t4 = tp[4], t5 = tp[5], t6 = tp[6], t7 = tp[7];

    int beg = g_rowptr[node], end = g_rowptr[node + 1];

    float m = __int_as_float(0xff800000);   // -inf
    float a = 0.f;
    float s0 = 0.f, s1 = 0.f, s2 = 0.f, s3 = 0.f;
    float s4 = 0.f, s5 = 0.f, s6 = 0.f, s7 = 0.f;  // s7 accumulates den

    for (int i = beg; i < end; i++) {
        int src = g_src_s[i];
        float kk = g_k[(size_t)src * HC + c];
        float vv = g_v[(size_t)src * HC + c];
        float4 ea0 = *(const float4*)(g_ea_s + (size_t)i * 8);
        float4 ea1 = *(const float4*)(g_ea_s + (size_t)i * 8 + 4);

        float p = qv * kk;
        p += __shfl_xor_sync(0xffffffffu, p, 8);
        p += __shfl_xor_sync(0xffffffffu, p, 4);
        p += __shfl_xor_sync(0xffffffffu, p, 2);
        p += __shfl_xor_sync(0xffffffffu, p, 1);

        float s = p;
        s = fmaf(ea0.x, t0, s);
        s = fmaf(ea0.y, t1, s);
        s = fmaf(ea0.z, t2, s);
        s = fmaf(ea0.w, t3, s);
        s = fmaf(ea1.x, t4, s);
        s = fmaf(ea1.y, t5, s);
        s = fmaf(ea1.z, t6, s);
        s = fmaf(ea1.w, t7, s);
        s *= 0.25f;   // 1/sqrt(16)

        float mn = fmaxf(m, s);
        float corr = __expf(m - mn);
        float ex = __expf(s - mn);
        a  = fmaf(a,  corr, ex * vv);
        s0 = fmaf(s0, corr, ex * ea0.x);
        s1 = fmaf(s1, corr, ex * ea0.y);
        s2 = fmaf(s2, corr, ex * ea0.z);
        s3 = fmaf(s3, corr, ex * ea0.w);
        s4 = fmaf(s4, corr, ex * ea1.x);
        s5 = fmaf(s5, corr, ex * ea1.y);
        s6 = fmaf(s6, corr, ex * ea1.z);
        s7 = fmaf(s7, corr, ex);        // ea1.w == 1
        m = mn;
    }

    float den = s7;
    float inv = (den > 0.f) ? 1.f / den : 0.f;
    float agg = a;
    agg = fmaf(s0, __ldg(We + 0 * HC + c), agg);
    agg = fmaf(s1, __ldg(We + 1 * HC + c), agg);
    agg = fmaf(s2, __ldg(We + 2 * HC + c), agg);
    agg = fmaf(s3, __ldg(We + 3 * HC + c), agg);
    agg = fmaf(s4, __ldg(We + 4 * HC + c), agg);
    agg = fmaf(s5, __ldg(We + 5 * HC + c), agg);
    agg = fmaf(s6, __ldg(We + 6 * HC + c), agg);
    agg = fmaf(s7, __ldg(be + c),          agg);   // bias term: den * be
    agg *= inv;

    size_t idx = (size_t)node * HC + c;
    g_h[idx] = leaky(g_skip[idx] + agg);
}

// ================= host orchestration =================
extern "C" void kernel_launch(void* const* d_in, const int* in_sizes, int n_in,
                              void* d_out, int out_size)
{
    const float* x   = (const float*)d_in[0];
    const int*   ei  = (const int*)  d_in[1];
    const float* ea  = (const float*)d_in[2];
    const float* Wq1 = (const float*)d_in[3];
    const float* bq1 = (const float*)d_in[4];
    const float* Wk1 = (const float*)d_in[5];
    const float* bk1 = (const float*)d_in[6];
    const float* Wv1 = (const float*)d_in[7];
    const float* bv1 = (const float*)d_in[8];
    const float* We1 = (const float*)d_in[9];
    const float* be1 = (const float*)d_in[10];
    const float* Ws1 = (const float*)d_in[11];
    const float* bs1 = (const float*)d_in[12];
    const float* Wqr = (const float*)d_in[13];
    const float* bqr = (const float*)d_in[14];
    const float* Wkr = (const float*)d_in[15];
    const float* bkr = (const float*)d_in[16];
    const float* Wvr = (const float*)d_in[17];
    const float* bvr = (const float*)d_in[18];
    const float* Wer = (const float*)d_in[19];
    const float* ber = (const float*)d_in[20];
    const float* Wsr = (const float*)d_in[21];
    const float* bsr = (const float*)d_in[22];
    const float* Wr1 = (const float*)d_in[23];
    const float* br1 = (const float*)d_in[24];
    const float* Wrm = (const float*)d_in[25];
    const float* brm = (const float*)d_in[26];
    const float* Wre = (const float*)d_in[27];
    const float* bre = (const float*)d_in[28];
    float* out = (float*)d_out;

    float *pq, *pk, *pv, *pskip, *ph, *pr1;
    cudaGetSymbolAddress((void**)&pq,    g_q);
    cudaGetSymbolAddress((void**)&pk,    g_k);
    cudaGetSymbolAddress((void**)&pv,    g_v);
    cudaGetSymbolAddress((void**)&pskip, g_skip);
    cudaGetSymbolAddress((void**)&ph,    g_h);
    cudaGetSymbolAddress((void**)&pr1,   g_r1);

    const int nodeBlocks  = (NN * HC + 255) / 256;
    const int edgeBlocks  = (EE + 255) / 256;
    const int aggBlocks   = (int)(((size_t)NN * 4 * 32 + 255) / 256);
    const int tBlocks     = (NN * 64 + 255) / 256;

    // ---- CSR build (once; reused by all 4 layers) ----
    csr_zero<<<(NN + 255) / 256, 256>>>();
    csr_hist<<<edgeBlocks, 256>>>(ei);
    csr_scan1<<<NBLK, SCAN_B>>>();
    csr_scan2<<<1, 32>>>();
    csr_scan3<<<(NN + 255) / 256, 256>>>();
    csr_scatter<<<edgeBlocks, 256>>>(ei, ea);

    // ---- layer 1 (input dim = 2) ----
    proj_first<<<nodeBlocks, 256>>>(x, Wq1, bq1, Wk1, bk1, Wv1, bv1, Ws1, bs1);
    t_compute<<<tBlocks, 256>>>(We1, be1);
    fused_aggregate<<<aggBlocks, 256>>>(We1, be1);

    // ---- layers 2..4 (input dim = 128) ----
    dim3 gQKV(1, (NN + BM - 1) / BM, 4);
    for (int i = 0; i < 3; i++) {
        const float* Wq = Wqr + (size_t)i * HC * HC;    const float* bq = bqr + i * HC;
        const float* Wk = Wkr + (size_t)i * HC * HC;    const float* bk = bkr + i * HC;
        const float* Wv = Wvr + (size_t)i * HC * HC;    const float* bv = bvr + i * HC;
        const float* We = Wer + (size_t)i * FEdim * HC; const float* be = ber + i * HC;
        const float* Ws = Wsr + (size_t)i * HC * HC;    const float* bs = bsr + i * HC;

        gemm_qkvs<<<gQKV, 256>>>(ph, Wq, bq, pq, Wk, bk, pk, Wv, bv, pv, Ws, bs, pskip);
        t_compute<<<tBlocks, 256>>>(We, be);
        fused_aggregate<<<aggBlocks, 256>>>(We, be);
    }

    // ---- regression head ----
    dim3 gH1((RH + BN - 1) / BN, (NN + BM - 1) / BM);
    gemm_bias_act<<<gH1, 256>>>(ph, Wr1, br1, pr1, NN, HC, RH, 1);
    out_init<<<(NN + 255) / 256, 256>>>(bre, out);
    gemm_head_tail<<<gH1, 256>>>(pr1, Wrm, brm, Wre, out);
}

// round 13
// speedup vs baseline: 1.1370x; 1.0258x over previous
#include <cuda_runtime.h>
#include <math.h>
#include <string.h>

// Fixed problem shapes
#define NN 50000
#define EE 800000
#define HH 8
#define CC 16
#define HC 128
#define FEdim 7
#define RH 500
#define SLOPE 0.01f
#define SCAN_B 1024
#define NBLK ((NN + SCAN_B - 1) / SCAN_B)   // 49

// ---------------- static device scratch ----------------
__device__ float g_q[NN * HC];
__device__ float g_k[NN * HC];
__device__ float g_v[NN * HC];
__device__ float g_skip[NN * HC];
__device__ float g_h[NN * HC];
__device__ float g_t[(size_t)NN * 64];          // per-node q-projected edge weights (8 heads x 8)
__device__ float g_r1[(size_t)NN * RH];
// CSR (built once, reused by all 4 layers)
__device__ int   g_cnt[NN];
__device__ int   g_scan[NN];
__device__ int   g_rowptr[NN + 1];
__device__ int   g_src_s[EE];                   // src node per sorted edge
__device__ float g_ea_s[(size_t)EE * 8];        // sorted edge attrs, padded, [7]=1.0
__device__ int   g_bsum[NBLK];

__device__ __forceinline__ float leaky(float v) { return v > 0.f ? v : SLOPE * v; }

// ---- packed f32x2 helpers (Blackwell FFMA2: only reachable via PTX) ----
__device__ __forceinline__ unsigned long long pack2(float x, float y) {
    unsigned long long r;
    asm("mov.b64 %0, {%1, %2};" : "=l"(r) : "f"(x), "f"(y));
    return r;
}
__device__ __forceinline__ void fma2(unsigned long long& d,
                                     unsigned long long a, unsigned long long b) {
    asm("fma.rn.f32x2 %0, %1, %2, %0;" : "+l"(d) : "l"(a), "l"(b));
}
__device__ __forceinline__ float2 unpack2(unsigned long long v) {
    float2 r;
    asm("mov.b64 {%0, %1}, %2;" : "=f"(r.x), "=f"(r.y) : "l"(v));
    return r;
}

// ================= CSR build =================
__global__ void csr_zero() {
    int i = blockIdx.x * blockDim.x + threadIdx.x;
    if (i < NN) g_cnt[i] = 0;
}
__global__ void csr_hist(const int* __restrict__ ei) {
    int i = blockIdx.x * blockDim.x + threadIdx.x;
    if (i < EE) atomicAdd(&g_cnt[ei[EE + i]], 1);
}
__global__ __launch_bounds__(SCAN_B) void csr_scan1() {
    __shared__ int s[SCAN_B];
    int t = threadIdx.x;
    int i = blockIdx.x * SCAN_B + t;
    int v = (i < NN) ? g_cnt[i] : 0;
    s[t] = v;
    __syncthreads();
    for (int off = 1; off < SCAN_B; off <<= 1) {
        int x = (t >= off) ? s[t - off] : 0;
        __syncthreads();
        s[t] += x;
        __syncthreads();
    }
    if (i < NN) g_scan[i] = s[t];
    if (t == SCAN_B - 1) g_bsum[blockIdx.x] = s[t];
}
__global__ void csr_scan2() {
    if (threadIdx.x == 0) {
        int run = 0;
        for (int b = 0; b < NBLK; b++) { int v = g_bsum[b]; g_bsum[b] = run; run += v; }
    }
}
__global__ void csr_scan3() {
    int i = blockIdx.x * blockDim.x + threadIdx.x;
    if (i < NN) {
        g_rowptr[i] = g_scan[i] - g_cnt[i] + g_bsum[i / SCAN_B];
        g_cnt[i] = 0;  // reuse as scatter cursor
    }
    if (i == 0) g_rowptr[NN] = EE;
}
__global__ void csr_scatter(const int* __restrict__ ei, const float* __restrict__ ea) {
    int e = blockIdx.x * blockDim.x + threadIdx.x;
    if (e >= EE) return;
    int d = ei[EE + e];
    int pos = g_rowptr[d] + atomicAdd(&g_cnt[d], 1);
    g_src_s[pos] = ei[e];
    const float* a = ea + (size_t)e * FEdim;
    float* o = g_ea_s + (size_t)pos * 8;
    o[0] = a[0]; o[1] = a[1]; o[2] = a[2]; o[3] = a[3];
    o[4] = a[4]; o[5] = a[5]; o[6] = a[6]; o[7] = 1.0f;   // pad = 1 folds bias via t[7]
}

// ======== generic fp32 GEMM: FFMA2 inner loop + global->reg prefetch ========
#define BM 128
#define BN 128
#define BK 16
#define TM 8
#define TN 8

// Accumulates into packed f32x2 acc2[row][colpair]; epilogue left to caller.
__device__ __forceinline__ void gemm_accum(
    const float* __restrict__ A, const float* __restrict__ W,
    int M, int K, int Nn, int bx, int by,
    unsigned long long (&acc2)[TM][TN / 2],
    float (*As)[BM + 4], float (*Bs)[BN])
{
    int tid = threadIdx.x;
    int row0 = by * BM;
    int col0 = bx * BN;
    int tx = tid & 15;
    int ty = tid >> 4;

    // k-invariant per-thread load coordinates
    int kkA[8], mA[8], kkB[8], nB[8];
#pragma unroll
    for (int i = 0; i < 8; i++) {
        int idx = tid + i * 256;
        kkA[i] = idx & 15;  mA[i] = idx >> 4;
        nB[i]  = idx & 127; kkB[i] = idx >> 7;
    }

    // prologue: load k0 = 0 tile into registers
    float ra[8], rb[8];
#pragma unroll
    for (int i = 0; i < 8; i++) {
        int gr = row0 + mA[i], gk = kkA[i];
        ra[i] = (gr < M && gk < K) ? A[(size_t)gr * K + gk] : 0.f;
        int gn = col0 + nB[i], gkb = kkB[i];
        rb[i] = (gkb < K && gn < Nn) ? W[(size_t)gkb * Nn + gn] : 0.f;
    }

    for (int k0 = 0; k0 < K; k0 += BK) {
        // commit current tile to smem
#pragma unroll
        for (int i = 0; i < 8; i++) {
            As[kkA[i]][mA[i]] = ra[i];
            Bs[kkB[i]][nB[i]] = rb[i];
        }
        __syncthreads();

        // prefetch next tile while computing this one
        int k1 = k0 + BK;
        if (k1 < K) {
#pragma unroll
            for (int i = 0; i < 8; i++) {
                int gr = row0 + mA[i], gk = k1 + kkA[i];
                ra[i] = (gr < M && gk < K) ? A[(size_t)gr * K + gk] : 0.f;
                int gn = col0 + nB[i], gkb = k1 + kkB[i];
                rb[i] = (gkb < K && gn < Nn) ? W[(size_t)gkb * Nn + gn] : 0.f;
            }
        }

#pragma unroll
        for (int kk = 0; kk < BK; kk++) {
            float4 a0 = *(const float4*)&As[kk][ty * TM];
            float4 a1 = *(const float4*)&As[kk][ty * TM + 4];
            float a[TM] = {a0.x, a0.y, a0.z, a0.w, a1.x, a1.y, a1.z, a1.w};
            float4 bb0 = *(const float4*)&Bs[kk][tx * TN];
            float4 bb1 = *(const float4*)&Bs[kk][tx * TN + 4];
            unsigned long long b2[4];
            memcpy(&b2[0], &bb0, 16);     // free: register reinterpret
            memcpy(&b2[2], &bb1, 16);
#pragma unroll
            for (int i = 0; i < TM; i++) {
                unsigned long long aa = pack2(a[i], a[i]);
#pragma unroll
                for (int j = 0; j < TN / 2; j++)
                    fma2(acc2[i][j], aa, b2[j]);
            }
        }
        __syncthreads();
    }
}

__device__ __forceinline__ void acc_unpack(
    const unsigned long long (&acc2)[TM][TN / 2], float (&acc)[TM][TN])
{
#pragma unroll
    for (int i = 0; i < TM; i++)
#pragma unroll
        for (int j = 0; j < TN / 2; j++) {
            float2 p = unpack2(acc2[i][j]);
            acc[i][2 * j]     = p.x;
            acc[i][2 * j + 1] = p.y;
        }
}

__global__ __launch_bounds__(256, 2) void gemm_bias_act(
    const float* __restrict__ A, const float* __restrict__ W,
    const float* __restrict__ bias, float* __restrict__ C,
    int M, int K, int Nn, int act)
{
    __shared__ float As[BK][BM + 4];
    __shared__ float Bs[BK][BN];
    unsigned long long acc2[TM][TN / 2];
#pragma unroll
    for (int i = 0; i < TM; i++)
#pragma unroll
        for (int j = 0; j < TN / 2; j++) acc2[i][j] = 0ull;

    gemm_accum(A, W, M, K, Nn, blockIdx.x, blockIdx.y, acc2, As, Bs);

    float acc[TM][TN];
    acc_unpack(acc2, acc);

    int tid = threadIdx.x;
    int tx = tid & 15, ty = tid >> 4;
    int row0 = blockIdx.y * BM, col0 = blockIdx.x * BN;
#pragma unroll
    for (int i = 0; i < TM; i++) {
        int gr = row0 + ty * TM + i;
        if (gr >= M) continue;
#pragma unroll
        for (int j = 0; j < TN; j++) {
            int gn = col0 + tx * TN + j;
            if (gn >= Nn) continue;
            float v = acc[i][j] + bias[gn];
            if (act) v = leaky(v);
            C[(size_t)gr * Nn + gn] = v;
        }
    }
}

// Fused 4-way projection: z selects {q,k,v,skip}
__global__ __launch_bounds__(256, 2) void gemm_qkvs(
    const float* __restrict__ A,
    const float* __restrict__ W0, const float* __restrict__ b0, float* __restrict__ C0,
    const float* __restrict__ W1, const float* __restrict__ b1, float* __restrict__ C1,
    const float* __restrict__ W2, const float* __restrict__ b2, float* __restrict__ C2,
    const float* __restrict__ W3, const float* __restrict__ b3, float* __restrict__ C3)
{
    const float* W; const float* b; float* C;
    switch (blockIdx.z) {
        case 0: W = W0; b = b0; C = C0; break;
        case 1: W = W1; b = b1; C = C1; break;
        case 2: W = W2; b = b2; C = C2; break;
        default: W = W3; b = b3; C = C3; break;
    }
    __shared__ float As[BK][BM + 4];
    __shared__ float Bs[BK][BN];
    unsigned long long acc2[TM][TN / 2];
#pragma unroll
    for (int i = 0; i < TM; i++)
#pragma unroll
        for (int j = 0; j < TN / 2; j++) acc2[i][j] = 0ull;

    gemm_accum(A, W, NN, HC, HC, blockIdx.x, blockIdx.y, acc2, As, Bs);

    float acc[TM][TN];
    acc_unpack(acc2, acc);

    int tid = threadIdx.x;
    int tx = tid & 15, ty = tid >> 4;
    int row0 = blockIdx.y * BM, col0 = blockIdx.x * BN;
#pragma unroll
    for (int i = 0; i < TM; i++) {
        int gr = row0 + ty * TM + i;
        if (gr >= NN) continue;
#pragma unroll
        for (int j = 0; j < TN; j++) {
            int gn = col0 + tx * TN + j;
            C[(size_t)gr * HC + gn] = acc[i][j] + b[gn];
        }
    }
}

// Fused tail: out[r] += sum_n leaky(r1[r,:]@Wrm[:,n] + brm[n]) * Wre[n]
__global__ __launch_bounds__(256, 2) void gemm_head_tail(
    const float* __restrict__ A, const float* __restrict__ W,
    const float* __restrict__ bias, const float* __restrict__ wre,
    float* __restrict__ out)
{
    __shared__ float As[BK][BM + 4];
    __shared__ float Bs[BK][BN];
    unsigned long long acc2[TM][TN / 2];
#pragma unroll
    for (int i = 0; i < TM; i++)
#pragma unroll
        for (int j = 0; j < TN / 2; j++) acc2[i][j] = 0ull;

    gemm_accum(A, W, NN, RH, RH, blockIdx.x, blockIdx.y, acc2, As, Bs);

    float acc[TM][TN];
    acc_unpack(acc2, acc);

    int tid = threadIdx.x;
    int tx = tid & 15, ty = tid >> 4;
    int row0 = blockIdx.y * BM, col0 = blockIdx.x * BN;

    float wr[TN], bi[TN];
#pragma unroll
    for (int j = 0; j < TN; j++) {
        int gn = col0 + tx * TN + j;
        wr[j] = (gn < RH) ? __ldg(wre + gn)  : 0.f;
        bi[j] = (gn < RH) ? __ldg(bias + gn) : 0.f;
    }

#pragma unroll
    for (int i = 0; i < TM; i++) {
        int gr = row0 + ty * TM + i;
        float p = 0.f;
#pragma unroll
        for (int j = 0; j < TN; j++)
            p = fmaf(leaky(acc[i][j] + bi[j]), wr[j], p);
        // reduce across the 16 tx lanes (same ty)
        p += __shfl_xor_sync(0xffffffffu, p, 1);
        p += __shfl_xor_sync(0xffffffffu, p, 2);
        p += __shfl_xor_sync(0xffffffffu, p, 4);
        p += __shfl_xor_sync(0xffffffffu, p, 8);
        if (tx == 0 && gr < NN) atomicAdd(out + gr, p);
    }
}

__global__ void out_init(const float* __restrict__ bre, float* __restrict__ out)
{
    int i = blockIdx.x * blockDim.x + threadIdx.x;
    if (i < NN) out[i] = __ldg(bre);
}

// ================= layer-1 projections (K = 2) =================
__global__ void proj_first(const float* __restrict__ x,
    const float* __restrict__ Wq, const float* __restrict__ bq,
    const float* __restrict__ Wk, const float* __restrict__ bk,
    const float* __restrict__ Wv, const float* __restrict__ bv,
    const float* __restrict__ Ws, const float* __restrict__ bs)
{
    int idx = blockIdx.x * blockDim.x + threadIdx.x;
    if (idx >= NN * HC) return;
    int n = idx >> 7, c = idx & 127;
    float x0 = x[n * 2], x1 = x[n * 2 + 1];
    g_q[idx]    = fmaf(x0, __ldg(Wq + c), fmaf(x1, __ldg(Wq + HC + c), __ldg(bq + c)));
    g_k[idx]    = fmaf(x0, __ldg(Wk + c), fmaf(x1, __ldg(Wk + HC + c), __ldg(bk + c)));
    g_v[idx]    = fmaf(x0, __ldg(Wv + c), fmaf(x1, __ldg(Wv + HC + c), __ldg(bv + c)));
    g_skip[idx] = fmaf(x0, __ldg(Ws + c), fmaf(x1, __ldg(Ws + HC + c), __ldg(bs + c)));
}

// ============ t = per-(node,head) projection of q through We/be ============
__global__ void t_compute(const float* __restrict__ We, const float* __restrict__ be)
{
    int idx = blockIdx.x * blockDim.x + threadIdx.x;   // n*64 + h*8 + f
    if (idx >= NN * 64) return;
    int f = idx & 7;
    int h = (idx >> 3) & 7;
    int n = idx >> 6;
    const float* w = (f < 7) ? (We + f * HC + h * 16) : (be + h * 16);
    const float* q = g_q + (size_t)n * HC + h * 16;
    float s = 0.f;
#pragma unroll
    for (int c = 0; c < 16; c++) s = fmaf(q[c], __ldg(w + c), s);
    g_t[idx] = s;
}

// ============ fused edge pass: online softmax + aggregation ============
// 4 warps per node; lane owns one channel c; warp covers 2 heads.
__global__ __launch_bounds__(256) void fused_aggregate(
    const float* __restrict__ We, const float* __restrict__ be)
{
    int gw = (int)((blockIdx.x * (size_t)blockDim.x + threadIdx.x) >> 5);
    int lane = threadIdx.x & 31;
    int node = gw >> 2;
    int qt = gw & 3;
    if (node >= NN) return;
    int c = qt * 32 + lane;
    int h = c >> 4;

    float qv = g_q[(size_t)node * HC + c];
    const float* tp = g_t + (size_t)node * 64 + h * 8;
    float t0 = tp[0], t1 = tp[1], t2 = tp[2], t3 = tp[3];
    float t4 = tp[4], t5 = tp[5], t6 = tp[6], t7 = tp[7];

    int beg = g_rowptr[node], end = g_rowptr[node + 1];

    float m = __int_as_float(0xff800000);   // -inf
    float a = 0.f;
    float s0 = 0.f, s1 = 0.f, s2 = 0.f, s3 = 0.f;
    float s4 = 0.f, s5 = 0.f, s6 = 0.f, s7 = 0.f;  // s7 accumulates den

    for (int i = beg; i < end; i++) {
        int src = g_src_s[i];
        float kk = g_k[(size_t)src * HC + c];
        float vv = g_v[(size_t)src * HC + c];
        float4 ea0 = *(const float4*)(g_ea_s + (size_t)i * 8);
        float4 ea1 = *(const float4*)(g_ea_s + (size_t)i * 8 + 4);

        float p = qv * kk;
        p += __shfl_xor_sync(0xffffffffu, p, 8);
        p += __shfl_xor_sync(0xffffffffu, p, 4);
        p += __shfl_xor_sync(0xffffffffu, p, 2);
        p += __shfl_xor_sync(0xffffffffu, p, 1);

        float s = p;
        s = fmaf(ea0.x, t0, s);
        s = fmaf(ea0.y, t1, s);
        s = fmaf(ea0.z, t2, s);
        s = fmaf(ea0.w, t3, s);
        s = fmaf(ea1.x, t4, s);
        s = fmaf(ea1.y, t5, s);
        s = fmaf(ea1.z, t6, s);
        s = fmaf(ea1.w, t7, s);
        s *= 0.25f;   // 1/sqrt(16)

        float mn = fmaxf(m, s);
        float corr = __expf(m - mn);
        float ex = __expf(s - mn);
        a  = fmaf(a,  corr, ex * vv);
        s0 = fmaf(s0, corr, ex * ea0.x);
        s1 = fmaf(s1, corr, ex * ea0.y);
        s2 = fmaf(s2, corr, ex * ea0.z);
        s3 = fmaf(s3, corr, ex * ea0.w);
        s4 = fmaf(s4, corr, ex * ea1.x);
        s5 = fmaf(s5, corr, ex * ea1.y);
        s6 = fmaf(s6, corr, ex * ea1.z);
        s7 = fmaf(s7, corr, ex);        // ea1.w == 1
        m = mn;
    }

    float den = s7;
    float inv = (den > 0.f) ? 1.f / den : 0.f;
    float agg = a;
    agg = fmaf(s0, __ldg(We + 0 * HC + c), agg);
    agg = fmaf(s1, __ldg(We + 1 * HC + c), agg);
    agg = fmaf(s2, __ldg(We + 2 * HC + c), agg);
    agg = fmaf(s3, __ldg(We + 3 * HC + c), agg);
    agg = fmaf(s4, __ldg(We + 4 * HC + c), agg);
    agg = fmaf(s5, __ldg(We + 5 * HC + c), agg);
    agg = fmaf(s6, __ldg(We + 6 * HC + c), agg);
    agg = fmaf(s7, __ldg(be + c),          agg);   // bias term: den * be
    agg *= inv;

    size_t idx = (size_t)node * HC + c;
    g_h[idx] = leaky(g_skip[idx] + agg);
}

// ================= host orchestration =================
extern "C" void kernel_launch(void* const* d_in, const int* in_sizes, int n_in,
                              void* d_out, int out_size)
{
    const float* x   = (const float*)d_in[0];
    const int*   ei  = (const int*)  d_in[1];
    const float* ea  = (const float*)d_in[2];
    const float* Wq1 = (const float*)d_in[3];
    const float* bq1 = (const float*)d_in[4];
    const float* Wk1 = (const float*)d_in[5];
    const float* bk1 = (const float*)d_in[6];
    const float* Wv1 = (const float*)d_in[7];
    const float* bv1 = (const float*)d_in[8];
    const float* We1 = (const float*)d_in[9];
    const float* be1 = (const float*)d_in[10];
    const float* Ws1 = (const float*)d_in[11];
    const float* bs1 = (const float*)d_in[12];
    const float* Wqr = (const float*)d_in[13];
    const float* bqr = (const float*)d_in[14];
    const float* Wkr = (const float*)d_in[15];
    const float* bkr = (const float*)d_in[16];
    const float* Wvr = (const float*)d_in[17];
    const float* bvr = (const float*)d_in[18];
    const float* Wer = (const float*)d_in[19];
    const float* ber = (const float*)d_in[20];
    const float* Wsr = (const float*)d_in[21];
    const float* bsr = (const float*)d_in[22];
    const float* Wr1 = (const float*)d_in[23];
    const float* br1 = (const float*)d_in[24];
    const float* Wrm = (const float*)d_in[25];
    const float* brm = (const float*)d_in[26];
    const float* Wre = (const float*)d_in[27];
    const float* bre = (const float*)d_in[28];
    float* out = (float*)d_out;

    float *pq, *pk, *pv, *pskip, *ph, *pr1;
    cudaGetSymbolAddress((void**)&pq,    g_q);
    cudaGetSymbolAddress((void**)&pk,    g_k);
    cudaGetSymbolAddress((void**)&pv,    g_v);
    cudaGetSymbolAddress((void**)&pskip, g_skip);
    cudaGetSymbolAddress((void**)&ph,    g_h);
    cudaGetSymbolAddress((void**)&pr1,   g_r1);

    const int nodeBlocks  = (NN * HC + 255) / 256;
    const int edgeBlocks  = (EE + 255) / 256;
    const int aggBlocks   = (int)(((size_t)NN * 4 * 32 + 255) / 256);
    const int tBlocks     = (NN * 64 + 255) / 256;

    // ---- CSR build (once; reused by all 4 layers) ----
    csr_zero<<<(NN + 255) / 256, 256>>>();
    csr_hist<<<edgeBlocks, 256>>>(ei);
    csr_scan1<<<NBLK, SCAN_B>>>();
    csr_scan2<<<1, 32>>>();
    csr_scan3<<<(NN + 255) / 256, 256>>>();
    csr_scatter<<<edgeBlocks, 256>>>(ei, ea);

    // ---- layer 1 (input dim = 2) ----
    proj_first<<<nodeBlocks, 256>>>(x, Wq1, bq1, Wk1, bk1, Wv1, bv1, Ws1, bs1);
    t_compute<<<tBlocks, 256>>>(We1, be1);
    fused_aggregate<<<aggBlocks, 256>>>(We1, be1);

    // ---- layers 2..4 (input dim = 128) ----
    dim3 gQKV(1, (NN + BM - 1) / BM, 4);
    for (int i = 0; i < 3; i++) {
        const float* Wq = Wqr + (size_t)i * HC * HC;    const float* bq = bqr + i * HC;
        const float* Wk = Wkr + (size_t)i * HC * HC;    const float* bk = bkr + i * HC;
        const float* Wv = Wvr + (size_t)i * HC * HC;    const float* bv = bvr + i * HC;
        const float* We = Wer + (size_t)i * FEdim * HC; const float* be = ber + i * HC;
        const float* Ws = Wsr + (size_t)i * HC * HC;    const float* bs = bsr + i * HC;

        gemm_qkvs<<<gQKV, 256>>>(ph, Wq, bq, pq, Wk, bk, pk, Wv, bv, pv, Ws, bs, pskip);
        t_compute<<<tBlocks, 256>>>(We, be);
        fused_aggregate<<<aggBlocks, 256>>>(We, be);
    }

    // ---- regression head ----
    dim3 gH1((RH + BN - 1) / BN, (NN + BM - 1) / BM);
    gemm_bias_act<<<gH1, 256>>>(ph, Wr1, br1, pr1, NN, HC, RH, 1);
    out_init<<<(NN + 255) / 256, 256>>>(bre, out);
    gemm_head_tail<<<gH1, 256>>>(pr1, Wrm, brm, Wre, out);
}

// round 15
// speedup vs baseline: 1.2037x; 1.0587x over previous
#include <cuda_runtime.h>
#include <math.h>

// Fixed problem shapes
#define NN 50000
#define EE 800000
#define HH 8
#define CC 16
#define HC 128
#define FEdim 7
#define RH 500
#define SLOPE 0.01f
#define SCAN_B 1024
#define NBLK ((NN + SCAN_B - 1) / SCAN_B)   // 49

// ---------------- static device scratch ----------------
__device__ float g_q[NN * HC];
__device__ float g_k[NN * HC];
__device__ float g_v[NN * HC];
__device__ float g_skip[NN * HC];
__device__ float g_h[NN * HC];
__device__ float g_t[(size_t)NN * 64];
__device__ float g_r1[(size_t)NN * RH];
// CSR (built once, reused by all 4 layers)
__device__ int   g_cnt[NN];
__device__ int   g_scan[NN];
__device__ int   g_rowptr[NN + 1];
__device__ int   g_src_s[EE];
__device__ float g_ea_s[(size_t)EE * 8];
__device__ int   g_bsum[NBLK];

__device__ __forceinline__ float leaky(float v) { return v > 0.f ? v : SLOPE * v; }

__device__ __forceinline__ unsigned f2tf32(float x) {
    unsigned u;
    asm("cvt.rna.tf32.f32 %0, %1;" : "=r"(u) : "f"(x));
    return u;
}
__device__ __forceinline__ void mma_tf32(float (&c)[4],
    unsigned a0, unsigned a1, unsigned a2, unsigned a3,
    unsigned b0, unsigned b1)
{
    asm volatile(
        "mma.sync.aligned.m16n8k8.row.col.f32.tf32.tf32.f32 "
        "{%0,%1,%2,%3}, {%4,%5,%6,%7}, {%8,%9}, {%0,%1,%2,%3};"
        : "+f"(c[0]), "+f"(c[1]), "+f"(c[2]), "+f"(c[3])
        : "r"(a0), "r"(a1), "r"(a2), "r"(a3), "r"(b0), "r"(b1));
}

// ================= CSR build =================
__global__ void csr_zero() {
    int i = blockIdx.x * blockDim.x + threadIdx.x;
    if (i < NN) g_cnt[i] = 0;
}
__global__ void csr_hist(const int* __restrict__ ei) {
    int i = blockIdx.x * blockDim.x + threadIdx.x;
    if (i < EE) atomicAdd(&g_cnt[ei[EE + i]], 1);
}
__global__ __launch_bounds__(SCAN_B) void csr_scan1() {
    __shared__ int s[SCAN_B];
    int t = threadIdx.x;
    int i = blockIdx.x * SCAN_B + t;
    int v = (i < NN) ? g_cnt[i] : 0;
    s[t] = v;
    __syncthreads();
    for (int off = 1; off < SCAN_B; off <<= 1) {
        int x = (t >= off) ? s[t - off] : 0;
        __syncthreads();
        s[t] += x;
        __syncthreads();
    }
    if (i < NN) g_scan[i] = s[t];
    if (t == SCAN_B - 1) g_bsum[blockIdx.x] = s[t];
}
__global__ void csr_scan2() {
    if (threadIdx.x == 0) {
        int run = 0;
        for (int b = 0; b < NBLK; b++) { int v = g_bsum[b]; g_bsum[b] = run; run += v; }
    }
}
__global__ void csr_scan3() {
    int i = blockIdx.x * blockDim.x + threadIdx.x;
    if (i < NN) {
        g_rowptr[i] = g_scan[i] - g_cnt[i] + g_bsum[i / SCAN_B];
        g_cnt[i] = 0;
    }
    if (i == 0) g_rowptr[NN] = EE;
}
__global__ void csr_scatter(const int* __restrict__ ei, const float* __restrict__ ea) {
    int e = blockIdx.x * blockDim.x + threadIdx.x;
    if (e >= EE) return;
    int d = ei[EE + e];
    int pos = g_rowptr[d] + atomicAdd(&g_cnt[d], 1);
    g_src_s[pos] = ei[e];
    const float* a = ea + (size_t)e * FEdim;
    float* o = g_ea_s + (size_t)pos * 8;
    o[0] = a[0]; o[1] = a[1]; o[2] = a[2]; o[3] = a[3];
    o[4] = a[4]; o[5] = a[5]; o[6] = a[6]; o[7] = 1.0f;
}

// == 3xTF32 tensor-core GEMM: 128x128 CTA tile, 8 warps (2x4), m16n8k8 ==
// Precision split: x = hi + lo, c += hi*hi + hi*lo + lo*hi  (~fp32 accuracy)
#define BM 128
#define BN 128
#define BK 16

__device__ __forceinline__ void gemm_accum_mma(
    const float* __restrict__ A, const float* __restrict__ W,
    int M, int K, int Nn, int bx, int by,
    float (&c)[4][4][4],
    unsigned (*Ah)[BM + 4], unsigned (*Al)[BM + 4],
    unsigned (*Bh)[BN + 4], unsigned (*Bl)[BN + 4])
{
    int tid  = threadIdx.x;
    int wid  = tid >> 5;
    int lane = tid & 31;
    int wm = wid & 1;
    int wn = wid >> 1;
    int gid  = lane >> 2;
    int tid4 = lane & 3;
    int row0 = by * BM;
    int col0 = bx * BN;

    // prologue: load k0 = 0 tile (coords recomputed inline to save regs)
    float ra[8], rb[8];
#pragma unroll
    for (int i = 0; i < 8; i++) {
        int idx = tid + i * 256;
        int gr = row0 + (idx >> 4), gk = idx & 15;
        ra[i] = (gr < M && gk < K) ? A[(size_t)gr * K + gk] : 0.f;
        int gn = col0 + (idx & 127), gkb = idx >> 7;
        rb[i] = (gkb < K && gn < Nn) ? W[(size_t)gkb * Nn + gn] : 0.f;
    }

    for (int k0 = 0; k0 < K; k0 += BK) {
        // commit current tile with hi/lo split
#pragma unroll
        for (int i = 0; i < 8; i++) {
            int idx = tid + i * 256;
            int kkA = idx & 15, mA = idx >> 4;
            unsigned h = f2tf32(ra[i]);
            Ah[kkA][mA] = h;
            Al[kkA][mA] = f2tf32(ra[i] - __uint_as_float(h));
            int nB = idx & 127, kkB = idx >> 7;
            unsigned hb = f2tf32(rb[i]);
            Bh[kkB][nB] = hb;
            Bl[kkB][nB] = f2tf32(rb[i] - __uint_as_float(hb));
        }
        __syncthreads();

        // prefetch next tile
        int k1 = k0 + BK;
        if (k1 < K) {
#pragma unroll
            for (int i = 0; i < 8; i++) {
                int idx = tid + i * 256;
                int gr = row0 + (idx >> 4), gk = k1 + (idx & 15);
                ra[i] = (gr < M && gk < K) ? A[(size_t)gr * K + gk] : 0.f;
                int gn = col0 + (idx & 127), gkb = k1 + (idx >> 7);
                rb[i] = (gkb < K && gn < Nn) ? W[(size_t)gkb * Nn + gn] : 0.f;
            }
        }

        // two k8 steps per BK=16 tile
#pragma unroll
        for (int ks = 0; ks < BK; ks += 8) {
            unsigned bh[4][2], bl[4][2];
#pragma unroll
            for (int nt = 0; nt < 4; nt++) {
                int cb = wn * 32 + nt * 8 + gid;
                bh[nt][0] = Bh[ks + tid4][cb];
                bh[nt][1] = Bh[ks + tid4 + 4][cb];
                bl[nt][0] = Bl[ks + tid4][cb];
                bl[nt][1] = Bl[ks + tid4 + 4][cb];
            }
#pragma unroll
            for (int mt = 0; mt < 4; mt++) {
                int rb0 = wm * 64 + mt * 16 + gid;
                unsigned ah0 = Ah[ks + tid4][rb0];
                unsigned ah1 = Ah[ks + tid4][rb0 + 8];
                unsigned ah2 = Ah[ks + tid4 + 4][rb0];
                unsigned ah3 = Ah[ks + tid4 + 4][rb0 + 8];
                unsigned al0 = Al[ks + tid4][rb0];
                unsigned al1 = Al[ks + tid4][rb0 + 8];
                unsigned al2 = Al[ks + tid4 + 4][rb0];
                unsigned al3 = Al[ks + tid4 + 4][rb0 + 8];
#pragma unroll
                for (int nt = 0; nt < 4; nt++) {
                    mma_tf32(c[mt][nt], ah0, ah1, ah2, ah3, bh[nt][0], bh[nt][1]);
                    mma_tf32(c[mt][nt], ah0, ah1, ah2, ah3, bl[nt][0], bl[nt][1]);
                    mma_tf32(c[mt][nt], al0, al1, al2, al3, bh[nt][0], bh[nt][1]);
                }
            }
        }
        __syncthreads();
    }
}

__global__ __launch_bounds__(256, 2) void gemm_bias_act(
    const float* __restrict__ A, const float* __restrict__ W,
    const float* __restrict__ bias, float* __restrict__ C,
    int M, int K, int Nn, int act)
{
    __shared__ unsigned Ah[BK][BM + 4];
    __shared__ unsigned Al[BK][BM + 4];
    __shared__ unsigned Bh[BK][BN + 4];
    __shared__ unsigned Bl[BK][BN + 4];
    float c[4][4][4];
#pragma unroll
    for (int a = 0; a < 4; a++)
#pragma unroll
        for (int b = 0; b < 4; b++)
#pragma unroll
            for (int d = 0; d < 4; d++) c[a][b][d] = 0.f;

    gemm_accum_mma(A, W, M, K, Nn, blockIdx.x, blockIdx.y, c, Ah, Al, Bh, Bl);

    int tid = threadIdx.x, wid = tid >> 5, lane = tid & 31;
    int wm = wid & 1, wn = wid >> 1, gid = lane >> 2, tid4 = lane & 3;
    int row0 = blockIdx.y * BM, col0 = blockIdx.x * BN;
#pragma unroll
    for (int mt = 0; mt < 4; mt++) {
        int r0 = row0 + wm * 64 + mt * 16 + gid;
        int r1 = r0 + 8;
#pragma unroll
        for (int nt = 0; nt < 4; nt++) {
            int cb = col0 + wn * 32 + nt * 8 + tid4 * 2;
#pragma unroll
            for (int j = 0; j < 2; j++) {
                int gn = cb + j;
                if (gn >= Nn) continue;
                float b = bias[gn];
                if (r0 < M) {
                    float v = c[mt][nt][j] + b;
                    C[(size_t)r0 * Nn + gn] = act ? leaky(v) : v;
                }
                if (r1 < M) {
                    float v = c[mt][nt][2 + j] + b;
                    C[(size_t)r1 * Nn + gn] = act ? leaky(v) : v;
                }
            }
        }
    }
}

// Fused 4-way projection: z selects {q,k,v,skip}
__global__ __launch_bounds__(256, 2) void gemm_qkvs(
    const float* __restrict__ A,
    const float* __restrict__ W0, const float* __restrict__ b0, float* __restrict__ C0,
    const float* __restrict__ W1, const float* __restrict__ b1, float* __restrict__ C1,
    const float* __restrict__ W2, const float* __restrict__ b2, float* __restrict__ C2,
    const float* __restrict__ W3, const float* __restrict__ b3, float* __restrict__ C3)
{
    const float* W; const float* bia; float* C;
    switch (blockIdx.z) {
        case 0: W = W0; bia = b0; C = C0; break;
        case 1: W = W1; bia = b1; C = C1; break;
        case 2: W = W2; bia = b2; C = C2; break;
        default: W = W3; bia = b3; C = C3; break;
    }
    __shared__ unsigned Ah[BK][BM + 4];
    __shared__ unsigned Al[BK][BM + 4];
    __shared__ unsigned Bh[BK][BN + 4];
    __shared__ unsigned Bl[BK][BN + 4];
    float c[4][4][4];
#pragma unroll
    for (int a = 0; a < 4; a++)
#pragma unroll
        for (int b = 0; b < 4; b++)
#pragma unroll
            for (int d = 0; d < 4; d++) c[a][b][d] = 0.f;

    gemm_accum_mma(A, W, NN, HC, HC, blockIdx.x, blockIdx.y, c, Ah, Al, Bh, Bl);

    int tid = threadIdx.x, wid = tid >> 5, lane = tid & 31;
    int wm = wid & 1, wn = wid >> 1, gid = lane >> 2, tid4 = lane & 3;
    int row0 = blockIdx.y * BM, col0 = blockIdx.x * BN;
#pragma unroll
    for (int mt = 0; mt < 4; mt++) {
        int r0 = row0 + wm * 64 + mt * 16 + gid;
        int r1 = r0 + 8;
#pragma unroll
        for (int nt = 0; nt < 4; nt++) {
            int cb = col0 + wn * 32 + nt * 8 + tid4 * 2;
            float bb0 = bia[cb], bb1 = bia[cb + 1];
            if (r0 < NN) {
                float2 v = make_float2(c[mt][nt][0] + bb0, c[mt][nt][1] + bb1);
                *(float2*)&C[(size_t)r0 * HC + cb] = v;
            }
            if (r1 < NN) {
                float2 v = make_float2(c[mt][nt][2] + bb0, c[mt][nt][3] + bb1);
                *(float2*)&C[(size_t)r1 * HC + cb] = v;
            }
        }
    }
}

// Fused tail: out[r] += sum_n leaky(r1[r,:]@Wrm[:,n] + brm[n]) * Wre[n]
__global__ __launch_bounds__(256, 2) void gemm_head_tail(
    const float* __restrict__ A, const float* __restrict__ W,
    const float* __restrict__ bias, const float* __restrict__ wre,
    float* __restrict__ out)
{
    __shared__ unsigned Ah[BK][BM + 4];
    __shared__ unsigned Al[BK][BM + 4];
    __shared__ unsigned Bh[BK][BN + 4];
    __shared__ unsigned Bl[BK][BN + 4];
    float c[4][4][4];
#pragma unroll
    for (int a = 0; a < 4; a++)
#pragma unroll
        for (int b = 0; b < 4; b++)
#pragma unroll
            for (int d = 0; d < 4; d++) c[a][b][d] = 0.f;

    gemm_accum_mma(A, W, NN, RH, RH, blockIdx.x, blockIdx.y, c, Ah, Al, Bh, Bl);

    int tid = threadIdx.x, wid = tid >> 5, lane = tid & 31;
    int wm = wid & 1, wn = wid >> 1, gid = lane >> 2, tid4 = lane & 3;
    int row0 = blockIdx.y * BM, col0 = blockIdx.x * BN;

    float bi[4][2], wr[4][2];
#pragma unroll
    for (int nt = 0; nt < 4; nt++)
#pragma unroll
        for (int j = 0; j < 2; j++) {
            int gn = col0 + wn * 32 + nt * 8 + tid4 * 2 + j;
            bi[nt][j] = (gn < RH) ? __ldg(bias + gn) : 0.f;
            wr[nt][j] = (gn < RH) ? __ldg(wre + gn)  : 0.f;
        }

#pragma unroll
    for (int mt = 0; mt < 4; mt++) {
        int r0 = row0 + wm * 64 + mt * 16 + gid;
        int r1 = r0 + 8;
        float p0 = 0.f, p1 = 0.f;
#pragma unroll
        for (int nt = 0; nt < 4; nt++)
#pragma unroll
            for (int j = 0; j < 2; j++) {
                p0 = fmaf(leaky(c[mt][nt][j]     + bi[nt][j]), wr[nt][j], p0);
                p1 = fmaf(leaky(c[mt][nt][2 + j] + bi[nt][j]), wr[nt][j], p1);
            }
        p0 += __shfl_xor_sync(0xffffffffu, p0, 1);
        p0 += __shfl_xor_sync(0xffffffffu, p0, 2);
        p1 += __shfl_xor_sync(0xffffffffu, p1, 1);
        p1 += __shfl_xor_sync(0xffffffffu, p1, 2);
        if (tid4 == 0) {
            if (r0 < NN) atomicAdd(out + r0, p0);
            if (r1 < NN) atomicAdd(out + r1, p1);
        }
    }
}

__global__ void out_init(const float* __restrict__ bre, float* __restrict__ out)
{
    int i = blockIdx.x * blockDim.x + threadIdx.x;
    if (i < NN) out[i] = __ldg(bre);
}

// ================= layer-1 projections (K = 2) =================
__global__ void proj_first(const float* __restrict__ x,
    const float* __restrict__ Wq, const float* __restrict__ bq,
    const float* __restrict__ Wk, const float* __restrict__ bk,
    const float* __restrict__ Wv, const float* __restrict__ bv,
    const float* __restrict__ Ws, const float* __restrict__ bs)
{
    int idx = blockIdx.x * blockDim.x + threadIdx.x;
    if (idx >= NN * HC) return;
    int n = idx >> 7, c = idx & 127;
    float x0 = x[n * 2], x1 = x[n * 2 + 1];
    g_q[idx]    = fmaf(x0, __ldg(Wq + c), fmaf(x1, __ldg(Wq + HC + c), __ldg(bq + c)));
    g_k[idx]    = fmaf(x0, __ldg(Wk + c), fmaf(x1, __ldg(Wk + HC + c), __ldg(bk + c)));
    g_v[idx]    = fmaf(x0, __ldg(Wv + c), fmaf(x1, __ldg(Wv + HC + c), __ldg(bv + c)));
    g_skip[idx] = fmaf(x0, __ldg(Ws + c), fmaf(x1, __ldg(Ws + HC + c), __ldg(bs + c)));
}

// ============ t = per-(node,head) projection of q through We/be ============
__global__ void t_compute(const float* __restrict__ We, const float* __restrict__ be)
{
    int idx = blockIdx.x * blockDim.x + threadIdx.x;   // n*64 + h*8 + f
    if (idx >= NN * 64) return;
    int f = idx & 7;
    int h = (idx >> 3) & 7;
    int n = idx >> 6;
    const float* w = (f < 7) ? (We + f * HC + h * 16) : (be + h * 16);
    const float* q = g_q + (size_t)n * HC + h * 16;
    float s = 0.f;
#pragma unroll
    for (int c = 0; c < 16; c++) s = fmaf(q[c], __ldg(w + c), s);
    g_t[idx] = s;
}

// ============ fused edge pass: online softmax + aggregation ============
__global__ __launch_bounds__(256) void fused_aggregate(
    const float* __restrict__ We, const float* __restrict__ be)
{
    int gw = (int)((blockIdx.x * (size_t)blockDim.x + threadIdx.x) >> 5);
    int lane = threadIdx.x & 31;
    int node = gw >> 2;
    int qt = gw & 3;
    if (node >= NN) return;
    int c = qt * 32 + lane;
    int h = c >> 4;

    float qv = g_q[(size_t)node * HC + c];
    const float* tp = g_t + (size_t)node * 64 + h * 8;
    float t0 = tp[0], t1 = tp[1], t2 = tp[2], t3 = tp[3];
    float t4 = tp[4], t5 = tp[5], t6 = tp[6], t7 = tp[7];

    int beg = g_rowptr[node], end = g_rowptr[node + 1];

    float m = __int_as_float(0xff800000);
    float a = 0.f;
    float s0 = 0.f, s1 = 0.f, s2 = 0.f, s3 = 0.f;
    float s4 = 0.f, s5 = 0.f, s6 = 0.f, s7 = 0.f;

    for (int i = beg; i < end; i++) {
        int src = g_src_s[i];
        float kk = g_k[(size_t)src * HC + c];
        float vv = g_v[(size_t)src * HC + c];
        float4 ea0 = *(const float4*)(g_ea_s + (size_t)i * 8);
        float4 ea1 = *(const float4*)(g_ea_s + (size_t)i * 8 + 4);

        float p = qv * kk;
        p += __shfl_xor_sync(0xffffffffu, p, 8);
        p += __shfl_xor_sync(0xffffffffu, p, 4);
        p += __shfl_xor_sync(0xffffffffu, p, 2);
        p += __shfl_xor_sync(0xffffffffu, p, 1);

        float s = p;
        s = fmaf(ea0.x, t0, s);
        s = fmaf(ea0.y, t1, s);
        s = fmaf(ea0.z, t2, s);
        s = fmaf(ea0.w, t3, s);
        s = fmaf(ea1.x, t4, s);
        s = fmaf(ea1.y, t5, s);
        s = fmaf(ea1.z, t6, s);
        s = fmaf(ea1.w, t7, s);
        s *= 0.25f;

        float mn = fmaxf(m, s);
        float corr = __expf(m - mn);
        float ex = __expf(s - mn);
        a  = fmaf(a,  corr, ex * vv);
        s0 = fmaf(s0, corr, ex * ea0.x);
        s1 = fmaf(s1, corr, ex * ea0.y);
        s2 = fmaf(s2, corr, ex * ea0.z);
        s3 = fmaf(s3, corr, ex * ea0.w);
        s4 = fmaf(s4, corr, ex * ea1.x);
        s5 = fmaf(s5, corr, ex * ea1.y);
        s6 = fmaf(s6, corr, ex * ea1.z);
        s7 = fmaf(s7, corr, ex);
        m = mn;
    }

    float den = s7;
    float inv = (den > 0.f) ? 1.f / den : 0.f;
    float agg = a;
    agg = fmaf(s0, __ldg(We + 0 * HC + c), agg);
    agg = fmaf(s1, __ldg(We + 1 * HC + c), agg);
    agg = fmaf(s2, __ldg(We + 2 * HC + c), agg);
    agg = fmaf(s3, __ldg(We + 3 * HC + c), agg);
    agg = fmaf(s4, __ldg(We + 4 * HC + c), agg);
    agg = fmaf(s5, __ldg(We + 5 * HC + c), agg);
    agg = fmaf(s6, __ldg(We + 6 * HC + c), agg);
    agg = fmaf(s7, __ldg(be + c),          agg);
    agg *= inv;

    size_t idx = (size_t)node * HC + c;
    g_h[idx] = leaky(g_skip[idx] + agg);
}

// ================= host orchestration =================
extern "C" void kernel_launch(void* const* d_in, const int* in_sizes, int n_in,
                              void* d_out, int out_size)
{
    const float* x   = (const float*)d_in[0];
    const int*   ei  = (const int*)  d_in[1];
    const float* ea  = (const float*)d_in[2];
    const float* Wq1 = (const float*)d_in[3];
    const float* bq1 = (const float*)d_in[4];
    const float* Wk1 = (const float*)d_in[5];
    const float* bk1 = (const float*)d_in[6];
    const float* Wv1 = (const float*)d_in[7];
    const float* bv1 = (const float*)d_in[8];
    const float* We1 = (const float*)d_in[9];
    const float* be1 = (const float*)d_in[10];
    const float* Ws1 = (const float*)d_in[11];
    const float* bs1 = (const float*)d_in[12];
    const float* Wqr = (const float*)d_in[13];
    const float* bqr = (const float*)d_in[14];
    const float* Wkr = (const float*)d_in[15];
    const float* bkr = (const float*)d_in[16];
    const float* Wvr = (const float*)d_in[17];
    const float* bvr = (const float*)d_in[18];
    const float* Wer = (const float*)d_in[19];
    const float* ber = (const float*)d_in[20];
    const float* Wsr = (const float*)d_in[21];
    const float* bsr = (const float*)d_in[22];
    const float* Wr1 = (const float*)d_in[23];
    const float* br1 = (const float*)d_in[24];
    const float* Wrm = (const float*)d_in[25];
    const float* brm = (const float*)d_in[26];
    const float* Wre = (const float*)d_in[27];
    const float* bre = (const float*)d_in[28];
    float* out = (float*)d_out;

    float *pq, *pk, *pv, *pskip, *ph, *pr1;
    cudaGetSymbolAddress((void**)&pq,    g_q);
    cudaGetSymbolAddress((void**)&pk,    g_k);
    cudaGetSymbolAddress((void**)&pv,    g_v);
    cudaGetSymbolAddress((void**)&pskip, g_skip);
    cudaGetSymbolAddress((void**)&ph,    g_h);
    cudaGetSymbolAddress((void**)&pr1,   g_r1);

    const int nodeBlocks  = (NN * HC + 255) / 256;
    const int edgeBlocks  = (EE + 255) / 256;
    const int aggBlocks   = (int)(((size_t)NN * 4 * 32 + 255) / 256);
    const int tBlocks     = (NN * 64 + 255) / 256;

    // ---- CSR build (once; reused by all 4 layers) ----
    csr_zero<<<(NN + 255) / 256, 256>>>();
    csr_hist<<<edgeBlocks, 256>>>(ei);
    csr_scan1<<<NBLK, SCAN_B>>>();
    csr_scan2<<<1, 32>>>();
    csr_scan3<<<(NN + 255) / 256, 256>>>();
    csr_scatter<<<edgeBlocks, 256>>>(ei, ea);

    // ---- layer 1 (input dim = 2) ----
    proj_first<<<nodeBlocks, 256>>>(x, Wq1, bq1, Wk1, bk1, Wv1, bv1, Ws1, bs1);
    t_compute<<<tBlocks, 256>>>(We1, be1);
    fused_aggregate<<<aggBlocks, 256>>>(We1, be1);

    // ---- layers 2..4 (input dim = 128), 3xTF32 tensor-core GEMMs ----
    dim3 gQKV(1, (NN + BM - 1) / BM, 4);
    for (int i = 0; i < 3; i++) {
        const float* Wq = Wqr + (size_t)i * HC * HC;    const float* bq = bqr + i * HC;
        const float* Wk = Wkr + (size_t)i * HC * HC;    const float* bk = bkr + i * HC;
        const float* Wv = Wvr + (size_t)i * HC * HC;    const float* bv = bvr + i * HC;
        const float* We = Wer + (size_t)i * FEdim * HC; const float* be = ber + i * HC;
        const float* Ws = Wsr + (size_t)i * HC * HC;    const float* bs = bsr + i * HC;

        gemm_qkvs<<<gQKV, 256>>>(ph, Wq, bq, pq, Wk, bk, pk, Wv, bv, pv, Ws, bs, pskip);
        t_compute<<<tBlocks, 256>>>(We, be);
        fused_aggregate<<<aggBlocks, 256>>>(We, be);
    }

    // ---- regression head ----
    dim3 gH1((RH + BN - 1) / BN, (NN + BM - 1) / BM);
    gemm_bias_act<<<gH1, 256>>>(ph, Wr1, br1, pr1, NN, HC, RH, 1);
    out_init<<<(NN + 255) / 256, 256>>>(bre, out);
    gemm_head_tail<<<gH1, 256>>>(pr1, Wrm, brm, Wre, out);
}

// round 16
// speedup vs baseline: 1.7066x; 1.4178x over previous
#include <cuda_runtime.h>
#include <math.h>

// Fixed problem shapes
#define NN 50000
#define EE 800000
#define HH 8
#define CC 16
#define HC 128
#define FEdim 7
#define RH 500
#define SLOPE 0.01f
#define SCAN_B 1024
#define NBLK ((NN + SCAN_B - 1) / SCAN_B)   // 49

// ---------------- static device scratch ----------------
__device__ float g_q[NN * HC];
__device__ float g_k[NN * HC];
__device__ float g_v[NN * HC];
__device__ float g_skip[NN * HC];
__device__ float g_h[NN * HC];
__device__ float g_t[(size_t)NN * 64];
__device__ float g_r1[(size_t)NN * RH];
// CSR (built once, reused by all 4 layers)
__device__ int   g_cnt[NN];
__device__ int   g_scan[NN];
__device__ int   g_rowptr[NN + 1];
__device__ int   g_src_s[EE];
__device__ float g_ea_s[(size_t)EE * 8];
__device__ int   g_bsum[NBLK];

__device__ __forceinline__ float leaky(float v) { return v > 0.f ? v : SLOPE * v; }

__device__ __forceinline__ unsigned f2tf32(float x) {
    unsigned u;
    asm("cvt.rna.tf32.f32 %0, %1;" : "=r"(u) : "f"(x));
    return u;
}
__device__ __forceinline__ void mma_tf32(float (&c)[4],
    unsigned a0, unsigned a1, unsigned a2, unsigned a3,
    unsigned b0, unsigned b1)
{
    asm volatile(
        "mma.sync.aligned.m16n8k8.row.col.f32.tf32.tf32.f32 "
        "{%0,%1,%2,%3}, {%4,%5,%6,%7}, {%8,%9}, {%0,%1,%2,%3};"
        : "+f"(c[0]), "+f"(c[1]), "+f"(c[2]), "+f"(c[3])
        : "r"(a0), "r"(a1), "r"(a2), "r"(a3), "r"(b0), "r"(b1));
}

// ================= CSR build =================
__global__ void csr_zero() {
    int i = blockIdx.x * blockDim.x + threadIdx.x;
    if (i < NN) g_cnt[i] = 0;
}
__global__ void csr_hist(const int* __restrict__ ei) {
    int i = blockIdx.x * blockDim.x + threadIdx.x;
    if (i < EE) atomicAdd(&g_cnt[ei[EE + i]], 1);
}
__global__ __launch_bounds__(SCAN_B) void csr_scan1() {
    __shared__ int s[SCAN_B];
    int t = threadIdx.x;
    int i = blockIdx.x * SCAN_B + t;
    int v = (i < NN) ? g_cnt[i] : 0;
    s[t] = v;
    __syncthreads();
    for (int off = 1; off < SCAN_B; off <<= 1) {
        int x = (t >= off) ? s[t - off] : 0;
        __syncthreads();
        s[t] += x;
        __syncthreads();
    }
    if (i < NN) g_scan[i] = s[t];
    if (t == SCAN_B - 1) g_bsum[blockIdx.x] = s[t];
}
__global__ void csr_scan2() {
    if (threadIdx.x == 0) {
        int run = 0;
        for (int b = 0; b < NBLK; b++) { int v = g_bsum[b]; g_bsum[b] = run; run += v; }
    }
}
__global__ void csr_scan3() {
    int i = blockIdx.x * blockDim.x + threadIdx.x;
    if (i < NN) {
        g_rowptr[i] = g_scan[i] - g_cnt[i] + g_bsum[i / SCAN_B];
        g_cnt[i] = 0;
    }
    if (i == 0) g_rowptr[NN] = EE;
}
__global__ void csr_scatter(const int* __restrict__ ei, const float* __restrict__ ea) {
    int e = blockIdx.x * blockDim.x + threadIdx.x;
    if (e >= EE) return;
    int d = ei[EE + e];
    int pos = g_rowptr[d] + atomicAdd(&g_cnt[d], 1);
    g_src_s[pos] = ei[e];
    const float* a = ea + (size_t)e * FEdim;
    float* o = g_ea_s + (size_t)pos * 8;
    o[0] = a[0]; o[1] = a[1]; o[2] = a[2]; o[3] = a[3];
    o[4] = a[4]; o[5] = a[5]; o[6] = a[6]; o[7] = 1.0f;
}

// == 3xTF32 tensor-core GEMM: 128x128 CTA tile, 8 warps (2x4), m16n8k8 ==
#define BM 128
#define BN 128
#define BK 16

__device__ __forceinline__ void gemm_accum_mma(
    const float* __restrict__ A, const float* __restrict__ W,
    int M, int K, int Nn, int bx, int by,
    float (&c)[4][4][4],
    unsigned (*Ah)[BM + 4], unsigned (*Al)[BM + 4],
    unsigned (*Bh)[BN + 4], unsigned (*Bl)[BN + 4])
{
    int tid  = threadIdx.x;
    int wid  = tid >> 5;
    int lane = tid & 31;
    int wm = wid & 1;
    int wn = wid >> 1;
    int gid  = lane >> 2;
    int tid4 = lane & 3;
    int row0 = by * BM;
    int col0 = bx * BN;

    float ra[8], rb[8];
#pragma unroll
    for (int i = 0; i < 8; i++) {
        int idx = tid + i * 256;
        int gr = row0 + (idx >> 4), gk = idx & 15;
        ra[i] = (gr < M && gk < K) ? A[(size_t)gr * K + gk] : 0.f;
        int gn = col0 + (idx & 127), gkb = idx >> 7;
        rb[i] = (gkb < K && gn < Nn) ? W[(size_t)gkb * Nn + gn] : 0.f;
    }

    for (int k0 = 0; k0 < K; k0 += BK) {
#pragma unroll
        for (int i = 0; i < 8; i++) {
            int idx = tid + i * 256;
            int kkA = idx & 15, mA = idx >> 4;
            unsigned h = f2tf32(ra[i]);
            Ah[kkA][mA] = h;
            Al[kkA][mA] = f2tf32(ra[i] - __uint_as_float(h));
            int nB = idx & 127, kkB = idx >> 7;
            unsigned hb = f2tf32(rb[i]);
            Bh[kkB][nB] = hb;
            Bl[kkB][nB] = f2tf32(rb[i] - __uint_as_float(hb));
        }
        __syncthreads();

        int k1 = k0 + BK;
        if (k1 < K) {
#pragma unroll
            for (int i = 0; i < 8; i++) {
                int idx = tid + i * 256;
                int gr = row0 + (idx >> 4), gk = k1 + (idx & 15);
                ra[i] = (gr < M && gk < K) ? A[(size_t)gr * K + gk] : 0.f;
                int gn = col0 + (idx & 127), gkb = k1 + (idx >> 7);
                rb[i] = (gkb < K && gn < Nn) ? W[(size_t)gkb * Nn + gn] : 0.f;
            }
        }

#pragma unroll
        for (int ks = 0; ks < BK; ks += 8) {
            unsigned bh[4][2], bl[4][2];
#pragma unroll
            for (int nt = 0; nt < 4; nt++) {
                int cb = wn * 32 + nt * 8 + gid;
                bh[nt][0] = Bh[ks + tid4][cb];
                bh[nt][1] = Bh[ks + tid4 + 4][cb];
                bl[nt][0] = Bl[ks + tid4][cb];
                bl[nt][1] = Bl[ks + tid4 + 4][cb];
            }
#pragma unroll
            for (int mt = 0; mt < 4; mt++) {
                int rb0 = wm * 64 + mt * 16 + gid;
                unsigned ah0 = Ah[ks + tid4][rb0];
                unsigned ah1 = Ah[ks + tid4][rb0 + 8];
                unsigned ah2 = Ah[ks + tid4 + 4][rb0];
                unsigned ah3 = Ah[ks + tid4 + 4][rb0 + 8];
                unsigned al0 = Al[ks + tid4][rb0];
                unsigned al1 = Al[ks + tid4][rb0 + 8];
                unsigned al2 = Al[ks + tid4 + 4][rb0];
                unsigned al3 = Al[ks + tid4 + 4][rb0 + 8];
#pragma unroll
                for (int nt = 0; nt < 4; nt++) {
                    mma_tf32(c[mt][nt], ah0, ah1, ah2, ah3, bh[nt][0], bh[nt][1]);
                    mma_tf32(c[mt][nt], ah0, ah1, ah2, ah3, bl[nt][0], bl[nt][1]);
                    mma_tf32(c[mt][nt], al0, al1, al2, al3, bh[nt][0], bh[nt][1]);
                }
            }
        }
        __syncthreads();
    }
}

__global__ __launch_bounds__(256, 2) void gemm_bias_act(
    const float* __restrict__ A, const float* __restrict__ W,
    const float* __restrict__ bias, float* __restrict__ C,
    int M, int K, int Nn, int act)
{
    __shared__ unsigned Ah[BK][BM + 4];
    __shared__ unsigned Al[BK][BM + 4];
    __shared__ unsigned Bh[BK][BN + 4];
    __shared__ unsigned Bl[BK][BN + 4];
    float c[4][4][4];
#pragma unroll
    for (int a = 0; a < 4; a++)
#pragma unroll
        for (int b = 0; b < 4; b++)
#pragma unroll
            for (int d = 0; d < 4; d++) c[a][b][d] = 0.f;

    gemm_accum_mma(A, W, M, K, Nn, blockIdx.x, blockIdx.y, c, Ah, Al, Bh, Bl);

    int tid = threadIdx.x, wid = tid >> 5, lane = tid & 31;
    int wm = wid & 1, wn = wid >> 1, gid = lane >> 2, tid4 = lane & 3;
    int row0 = blockIdx.y * BM, col0 = blockIdx.x * BN;
#pragma unroll
    for (int mt = 0; mt < 4; mt++) {
        int r0 = row0 + wm * 64 + mt * 16 + gid;
        int r1 = r0 + 8;
#pragma unroll
        for (int nt = 0; nt < 4; nt++) {
            int cb = col0 + wn * 32 + nt * 8 + tid4 * 2;
#pragma unroll
            for (int j = 0; j < 2; j++) {
                int gn = cb + j;
                if (gn >= Nn) continue;
                float b = bias[gn];
                if (r0 < M) {
                    float v = c[mt][nt][j] + b;
                    C[(size_t)r0 * Nn + gn] = act ? leaky(v) : v;
                }
                if (r1 < M) {
                    float v = c[mt][nt][2 + j] + b;
                    C[(size_t)r1 * Nn + gn] = act ? leaky(v) : v;
                }
            }
        }
    }
}

// Fused 4-way projection: z selects {q,k,v,skip}
__global__ __launch_bounds__(256, 2) void gemm_qkvs(
    const float* __restrict__ A,
    const float* __restrict__ W0, const float* __restrict__ b0, float* __restrict__ C0,
    const float* __restrict__ W1, const float* __restrict__ b1, float* __restrict__ C1,
    const float* __restrict__ W2, const float* __restrict__ b2, float* __restrict__ C2,
    const float* __restrict__ W3, const float* __restrict__ b3, float* __restrict__ C3)
{
    const float* W; const float* bia; float* C;
    switch (blockIdx.z) {
        case 0: W = W0; bia = b0; C = C0; break;
        case 1: W = W1; bia = b1; C = C1; break;
        case 2: W = W2; bia = b2; C = C2; break;
        default: W = W3; bia = b3; C = C3; break;
    }
    __shared__ unsigned Ah[BK][BM + 4];
    __shared__ unsigned Al[BK][BM + 4];
    __shared__ unsigned Bh[BK][BN + 4];
    __shared__ unsigned Bl[BK][BN + 4];
    float c[4][4][4];
#pragma unroll
    for (int a = 0; a < 4; a++)
#pragma unroll
        for (int b = 0; b < 4; b++)
#pragma unroll
            for (int d = 0; d < 4; d++) c[a][b][d] = 0.f;

    gemm_accum_mma(A, W, NN, HC, HC, blockIdx.x, blockIdx.y, c, Ah, Al, Bh, Bl);

    int tid = threadIdx.x, wid = tid >> 5, lane = tid & 31;
    int wm = wid & 1, wn = wid >> 1, gid = lane >> 2, tid4 = lane & 3;
    int row0 = blockIdx.y * BM, col0 = blockIdx.x * BN;
#pragma unroll
    for (int mt = 0; mt < 4; mt++) {
        int r0 = row0 + wm * 64 + mt * 16 + gid;
        int r1 = r0 + 8;
#pragma unroll
        for (int nt = 0; nt < 4; nt++) {
            int cb = col0 + wn * 32 + nt * 8 + tid4 * 2;
            float bb0 = bia[cb], bb1 = bia[cb + 1];
            if (r0 < NN) {
                float2 v = make_float2(c[mt][nt][0] + bb0, c[mt][nt][1] + bb1);
                *(float2*)&C[(size_t)r0 * HC + cb] = v;
            }
            if (r1 < NN) {
                float2 v = make_float2(c[mt][nt][2] + bb0, c[mt][nt][3] + bb1);
                *(float2*)&C[(size_t)r1 * HC + cb] = v;
            }
        }
    }
}

// Fused tail: out[r] += sum_n leaky(r1[r,:]@Wrm[:,n] + brm[n]) * Wre[n]
__global__ __launch_bounds__(256, 2) void gemm_head_tail(
    const float* __restrict__ A, const float* __restrict__ W,
    const float* __restrict__ bias, const float* __restrict__ wre,
    float* __restrict__ out)
{
    __shared__ unsigned Ah[BK][BM + 4];
    __shared__ unsigned Al[BK][BM + 4];
    __shared__ unsigned Bh[BK][BN + 4];
    __shared__ unsigned Bl[BK][BN + 4];
    float c[4][4][4];
#pragma unroll
    for (int a = 0; a < 4; a++)
#pragma unroll
        for (int b = 0; b < 4; b++)
#pragma unroll
            for (int d = 0; d < 4; d++) c[a][b][d] = 0.f;

    gemm_accum_mma(A, W, NN, RH, RH, blockIdx.x, blockIdx.y, c, Ah, Al, Bh, Bl);

    int tid = threadIdx.x, wid = tid >> 5, lane = tid & 31;
    int wm = wid & 1, wn = wid >> 1, gid = lane >> 2, tid4 = lane & 3;
    int row0 = blockIdx.y * BM, col0 = blockIdx.x * BN;

    float bi[4][2], wr[4][2];
#pragma unroll
    for (int nt = 0; nt < 4; nt++)
#pragma unroll
        for (int j = 0; j < 2; j++) {
            int gn = col0 + wn * 32 + nt * 8 + tid4 * 2 + j;
            bi[nt][j] = (gn < RH) ? __ldg(bias + gn) : 0.f;
            wr[nt][j] = (gn < RH) ? __ldg(wre + gn)  : 0.f;
        }

#pragma unroll
    for (int mt = 0; mt < 4; mt++) {
        int r0 = row0 + wm * 64 + mt * 16 + gid;
        int r1 = r0 + 8;
        float p0 = 0.f, p1 = 0.f;
#pragma unroll
        for (int nt = 0; nt < 4; nt++)
#pragma unroll
            for (int j = 0; j < 2; j++) {
                p0 = fmaf(leaky(c[mt][nt][j]     + bi[nt][j]), wr[nt][j], p0);
                p1 = fmaf(leaky(c[mt][nt][2 + j] + bi[nt][j]), wr[nt][j], p1);
            }
        p0 += __shfl_xor_sync(0xffffffffu, p0, 1);
        p0 += __shfl_xor_sync(0xffffffffu, p0, 2);
        p1 += __shfl_xor_sync(0xffffffffu, p1, 1);
        p1 += __shfl_xor_sync(0xffffffffu, p1, 2);
        if (tid4 == 0) {
            if (r0 < NN) atomicAdd(out + r0, p0);
            if (r1 < NN) atomicAdd(out + r1, p1);
        }
    }
}

__global__ void out_init(const float* __restrict__ bre, float* __restrict__ out)
{
    int i = blockIdx.x * blockDim.x + threadIdx.x;
    if (i < NN) out[i] = __ldg(bre);
}

// ================= layer-1 projections (K = 2) =================
__global__ void proj_first(const float* __restrict__ x,
    const float* __restrict__ Wq, const float* __restrict__ bq,
    const float* __restrict__ Wk, const float* __restrict__ bk,
    const float* __restrict__ Wv, const float* __restrict__ bv,
    const float* __restrict__ Ws, const float* __restrict__ bs)
{
    int idx = blockIdx.x * blockDim.x + threadIdx.x;
    if (idx >= NN * HC) return;
    int n = idx >> 7, c = idx & 127;
    float x0 = x[n * 2], x1 = x[n * 2 + 1];
    g_q[idx]    = fmaf(x0, __ldg(Wq + c), fmaf(x1, __ldg(Wq + HC + c), __ldg(bq + c)));
    g_k[idx]    = fmaf(x0, __ldg(Wk + c), fmaf(x1, __ldg(Wk + HC + c), __ldg(bk + c)));
    g_v[idx]    = fmaf(x0, __ldg(Wv + c), fmaf(x1, __ldg(Wv + HC + c), __ldg(bv + c)));
    g_skip[idx] = fmaf(x0, __ldg(Ws + c), fmaf(x1, __ldg(Ws + HC + c), __ldg(bs + c)));
}

// ============ t = per-(node,head) projection of q through We/be ============
__global__ void t_compute(const float* __restrict__ We, const float* __restrict__ be)
{
    int idx = blockIdx.x * blockDim.x + threadIdx.x;   // n*64 + h*8 + f
    if (idx >= NN * 64) return;
    int f = idx & 7;
    int h = (idx >> 3) & 7;
    int n = idx >> 6;
    const float* w = (f < 7) ? (We + f * HC + h * 16) : (be + h * 16);
    const float* q = g_q + (size_t)n * HC + h * 16;
    float s = 0.f;
#pragma unroll
    for (int c = 0; c < 16; c++) s = fmaf(q[c], __ldg(w + c), s);
    g_t[idx] = s;
}

// ============ fused edge pass: 1 warp/node, float4 per lane ============
// lane owns channels c0..c0+3 (c0 = lane*4); head = lane>>2; quad shfl dot.
__global__ __launch_bounds__(256) void fused_aggregate(
    const float* __restrict__ We, const float* __restrict__ be)
{
    int node = (int)((blockIdx.x * (size_t)blockDim.x + threadIdx.x) >> 5);
    int lane = threadIdx.x & 31;
    if (node >= NN) return;
    int c0 = lane * 4;
    int h  = lane >> 2;

    float4 q4 = *(const float4*)(g_q + (size_t)node * HC + c0);
    const float* tp = g_t + (size_t)node * 64 + h * 8;
    float t0 = tp[0], t1 = tp[1], t2 = tp[2], t3 = tp[3];
    float t4 = tp[4], t5 = tp[5], t6 = tp[6], t7 = tp[7];

    int beg = g_rowptr[node], end = g_rowptr[node + 1];

    float m = __int_as_float(0xff800000);
    float a0 = 0.f, a1 = 0.f, a2 = 0.f, a3 = 0.f;
    float s0 = 0.f, s1 = 0.f, s2 = 0.f, s3 = 0.f;
    float s4 = 0.f, s5 = 0.f, s6 = 0.f, s7 = 0.f;   // s7 = den (ea[7]==1)

    for (int i = beg; i < end; i++) {
        int src = g_src_s[i];
        float4 k4 = *(const float4*)(g_k + (size_t)src * HC + c0);
        float4 v4 = *(const float4*)(g_v + (size_t)src * HC + c0);
        float4 ea0 = *(const float4*)(g_ea_s + (size_t)i * 8);
        float4 ea1 = *(const float4*)(g_ea_s + (size_t)i * 8 + 4);

        // per-head q.k dot: partial over 4 channels, reduce over 4-lane quad
        float p = q4.x * k4.x + q4.y * k4.y + q4.z * k4.z + q4.w * k4.w;
        p += __shfl_xor_sync(0xffffffffu, p, 1);
        p += __shfl_xor_sync(0xffffffffu, p, 2);

        float s = p;
        s = fmaf(ea0.x, t0, s);
        s = fmaf(ea0.y, t1, s);
        s = fmaf(ea0.z, t2, s);
        s = fmaf(ea0.w, t3, s);
        s = fmaf(ea1.x, t4, s);
        s = fmaf(ea1.y, t5, s);
        s = fmaf(ea1.z, t6, s);
        s = fmaf(ea1.w, t7, s);
        s *= 0.25f;                     // 1/sqrt(16)

        float mn = fmaxf(m, s);
        float corr = __expf(m - mn);
        float ex = __expf(s - mn);
        a0 = fmaf(a0, corr, ex * v4.x);
        a1 = fmaf(a1, corr, ex * v4.y);
        a2 = fmaf(a2, corr, ex * v4.z);
        a3 = fmaf(a3, corr, ex * v4.w);
        s0 = fmaf(s0, corr, ex * ea0.x);
        s1 = fmaf(s1, corr, ex * ea0.y);
        s2 = fmaf(s2, corr, ex * ea0.z);
        s3 = fmaf(s3, corr, ex * ea0.w);
        s4 = fmaf(s4, corr, ex * ea1.x);
        s5 = fmaf(s5, corr, ex * ea1.y);
        s6 = fmaf(s6, corr, ex * ea1.z);
        s7 = fmaf(s7, corr, ex);
        m = mn;
    }

    float den = s7;
    float inv = (den > 0.f) ? 1.f / den : 0.f;

    float4 sk = *(const float4*)(g_skip + (size_t)node * HC + c0);
    float r[4] = {a0, a1, a2, a3};
    float skv[4] = {sk.x, sk.y, sk.z, sk.w};
    float4 outv;
    float* op = (float*)&outv;
#pragma unroll
    for (int j = 0; j < 4; j++) {
        int c = c0 + j;
        float agg = r[j];
        agg = fmaf(s0, __ldg(We + 0 * HC + c), agg);
        agg = fmaf(s1, __ldg(We + 1 * HC + c), agg);
        agg = fmaf(s2, __ldg(We + 2 * HC + c), agg);
        agg = fmaf(s3, __ldg(We + 3 * HC + c), agg);
        agg = fmaf(s4, __ldg(We + 4 * HC + c), agg);
        agg = fmaf(s5, __ldg(We + 5 * HC + c), agg);
        agg = fmaf(s6, __ldg(We + 6 * HC + c), agg);
        agg = fmaf(s7, __ldg(be + c),          agg);
        op[j] = leaky(skv[j] + agg * inv);
    }
    // NOTE: reference computes (agg)/den then +skip; agg*inv == agg/den here
    *(float4*)(g_h + (size_t)node * HC + c0) = outv;
}

// ================= host orchestration =================
extern "C" void kernel_launch(void* const* d_in, const int* in_sizes, int n_in,
                              void* d_out, int out_size)
{
    const float* x   = (const float*)d_in[0];
    const int*   ei  = (const int*)  d_in[1];
    const float* ea  = (const float*)d_in[2];
    const float* Wq1 = (const float*)d_in[3];
    const float* bq1 = (const float*)d_in[4];
    const float* Wk1 = (const float*)d_in[5];
    const float* bk1 = (const float*)d_in[6];
    const float* Wv1 = (const float*)d_in[7];
    const float* bv1 = (const float*)d_in[8];
    const float* We1 = (const float*)d_in[9];
    const float* be1 = (const float*)d_in[10];
    const float* Ws1 = (const float*)d_in[11];
    const float* bs1 = (const float*)d_in[12];
    const float* Wqr = (const float*)d_in[13];
    const float* bqr = (const float*)d_in[14];
    const float* Wkr = (const float*)d_in[15];
    const float* bkr = (const float*)d_in[16];
    const float* Wvr = (const float*)d_in[17];
    const float* bvr = (const float*)d_in[18];
    const float* Wer = (const float*)d_in[19];
    const float* ber = (const float*)d_in[20];
    const float* Wsr = (const float*)d_in[21];
    const float* bsr = (const float*)d_in[22];
    const float* Wr1 = (const float*)d_in[23];
    const float* br1 = (const float*)d_in[24];
    const float* Wrm = (const float*)d_in[25];
    const float* brm = (const float*)d_in[26];
    const float* Wre = (const float*)d_in[27];
    const float* bre = (const float*)d_in[28];
    float* out = (float*)d_out;

    float *pq, *pk, *pv, *pskip, *ph, *pr1;
    cudaGetSymbolAddress((void**)&pq,    g_q);
    cudaGetSymbolAddress((void**)&pk,    g_k);
    cudaGetSymbolAddress((void**)&pv,    g_v);
    cudaGetSymbolAddress((void**)&pskip, g_skip);
    cudaGetSymbolAddress((void**)&ph,    g_h);
    cudaGetSymbolAddress((void**)&pr1,   g_r1);

    const int nodeBlocks  = (NN * HC + 255) / 256;
    const int edgeBlocks  = (EE + 255) / 256;
    const int aggBlocks   = (int)(((size_t)NN * 32 + 255) / 256);
    const int tBlocks     = (NN * 64 + 255) / 256;

    // ---- CSR build (once; reused by all 4 layers) ----
    csr_zero<<<(NN + 255) / 256, 256>>>();
    csr_hist<<<edgeBlocks, 256>>>(ei);
    csr_scan1<<<NBLK, SCAN_B>>>();
    csr_scan2<<<1, 32>>>();
    csr_scan3<<<(NN + 255) / 256, 256>>>();
    csr_scatter<<<edgeBlocks, 256>>>(ei, ea);

    // ---- layer 1 (input dim = 2) ----
    proj_first<<<nodeBlocks, 256>>>(x, Wq1, bq1, Wk1, bk1, Wv1, bv1, Ws1, bs1);
    t_compute<<<tBlocks, 256>>>(We1, be1);
    fused_aggregate<<<aggBlocks, 256>>>(We1, be1);

    // ---- layers 2..4 (input dim = 128), 3xTF32 tensor-core GEMMs ----
    dim3 gQKV(1, (NN + BM - 1) / BM, 4);
    for (int i = 0; i < 3; i++) {
        const float* Wq = Wqr + (size_t)i * HC * HC;    const float* bq = bqr + i * HC;
        const float* Wk = Wkr + (size_t)i * HC * HC;    const float* bk = bkr + i * HC;
        const float* Wv = Wvr + (size_t)i * HC * HC;    const float* bv = bvr + i * HC;
        const float* We = Wer + (size_t)i * FEdim * HC; const float* be = ber + i * HC;
        const float* Ws = Wsr + (size_t)i * HC * HC;    const float* bs = bsr + i * HC;

        gemm_qkvs<<<gQKV, 256>>>(ph, Wq, bq, pq, Wk, bk, pk, Wv, bv, pv, Ws, bs, pskip);
        t_compute<<<tBlocks, 256>>>(We, be);
        fused_aggregate<<<aggBlocks, 256>>>(We, be);
    }

    // ---- regression head ----
    dim3 gH1((RH + BN - 1) / BN, (NN + BM - 1) / BM);
    gemm_bias_act<<<gH1, 256>>>(ph, Wr1, br1, pr1, NN, HC, RH, 1);
    out_init<<<(NN + 255) / 256, 256>>>(bre, out);
    gemm_head_tail<<<gH1, 256>>>(pr1, Wrm, brm, Wre, out);
}

// round 17
// speedup vs baseline: 1.9634x; 1.1504x over previous
#include <cuda_runtime.h>
#include <math.h>

// Fixed problem shapes
#define NN 50000
#define EE 800000
#define HH 8
#define CC 16
#define HC 128
#define FEdim 7
#define RH 500
#define SLOPE 0.01f
#define SCAN_B 1024
#define NBLK ((NN + SCAN_B - 1) / SCAN_B)   // 49

// ---------------- static device scratch ----------------
__device__ float g_q[NN * HC];
__device__ float g_k[NN * HC];
__device__ float g_v[NN * HC];
__device__ float g_skip[NN * HC];
__device__ float g_h[NN * HC];
__device__ float g_t[(size_t)NN * 64];
__device__ float g_r1[(size_t)NN * RH];
// CSR (built once, reused by all 4 layers)
__device__ int   g_cnt[NN];
__device__ int   g_scan[NN];
__device__ int   g_rowptr[NN + 1];
__device__ int   g_src_s[EE];
__device__ float g_ea_s[(size_t)EE * 8];
__device__ int   g_bsum[NBLK];

__device__ __forceinline__ float leaky(float v) { return v > 0.f ? v : SLOPE * v; }

__device__ __forceinline__ unsigned f2tf32(float x) {
    unsigned u;
    asm("cvt.rna.tf32.f32 %0, %1;" : "=r"(u) : "f"(x));
    return u;
}
__device__ __forceinline__ void mma_tf32(float (&c)[4],
    unsigned a0, unsigned a1, unsigned a2, unsigned a3,
    unsigned b0, unsigned b1)
{
    asm volatile(
        "mma.sync.aligned.m16n8k8.row.col.f32.tf32.tf32.f32 "
        "{%0,%1,%2,%3}, {%4,%5,%6,%7}, {%8,%9}, {%0,%1,%2,%3};"
        : "+f"(c[0]), "+f"(c[1]), "+f"(c[2]), "+f"(c[3])
        : "r"(a0), "r"(a1), "r"(a2), "r"(a3), "r"(b0), "r"(b1));
}

// ================= CSR build =================
__global__ void csr_zero() {
    int i = blockIdx.x * blockDim.x + threadIdx.x;
    if (i < NN) g_cnt[i] = 0;
}
__global__ void csr_hist(const int* __restrict__ ei) {
    int i = blockIdx.x * blockDim.x + threadIdx.x;
    if (i < EE) atomicAdd(&g_cnt[ei[EE + i]], 1);
}
__global__ __launch_bounds__(SCAN_B) void csr_scan1() {
    __shared__ int s[SCAN_B];
    int t = threadIdx.x;
    int i = blockIdx.x * SCAN_B + t;
    int v = (i < NN) ? g_cnt[i] : 0;
    s[t] = v;
    __syncthreads();
    for (int off = 1; off < SCAN_B; off <<= 1) {
        int x = (t >= off) ? s[t - off] : 0;
        __syncthreads();
        s[t] += x;
        __syncthreads();
    }
    if (i < NN) g_scan[i] = s[t];
    if (t == SCAN_B - 1) g_bsum[blockIdx.x] = s[t];
}
__global__ void csr_scan2() {
    if (threadIdx.x == 0) {
        int run = 0;
        for (int b = 0; b < NBLK; b++) { int v = g_bsum[b]; g_bsum[b] = run; run += v; }
    }
}
__global__ void csr_scan3() {
    int i = blockIdx.x * blockDim.x + threadIdx.x;
    if (i < NN) {
        g_rowptr[i] = g_scan[i] - g_cnt[i] + g_bsum[i / SCAN_B];
        g_cnt[i] = 0;
    }
    if (i == 0) g_rowptr[NN] = EE;
}
__global__ void csr_scatter(const int* __restrict__ ei, const float* __restrict__ ea) {
    int e = blockIdx.x * blockDim.x + threadIdx.x;
    if (e >= EE) return;
    int d = ei[EE + e];
    int pos = g_rowptr[d] + atomicAdd(&g_cnt[d], 1);
    g_src_s[pos] = ei[e];
    const float* a = ea + (size_t)e * FEdim;
    float* o = g_ea_s + (size_t)pos * 8;
    o[0] = a[0]; o[1] = a[1]; o[2] = a[2]; o[3] = a[3];
    o[4] = a[4]; o[5] = a[5]; o[6] = a[6]; o[7] = 1.0f;
}

// == TF32 tensor-core GEMM: 128x128 CTA tile, 8 warps (2x4), m16n8k8 ==
// SPLIT=true: 3xTF32 precision split (~fp32).  SPLIT=false: plain tf32.
#define BM 128
#define BN 128
#define BK 16

template <bool SPLIT>
__device__ __forceinline__ void gemm_accum_mma(
    const float* __restrict__ A, const float* __restrict__ W,
    int M, int K, int Nn, int bx, int by,
    float (&c)[4][4][4],
    unsigned (*Ah)[BM + 4], unsigned (*Al)[BM + 4],
    unsigned (*Bh)[BN + 4], unsigned (*Bl)[BN + 4])
{
    int tid  = threadIdx.x;
    int wid  = tid >> 5;
    int lane = tid & 31;
    int wm = wid & 1;
    int wn = wid >> 1;
    int gid  = lane >> 2;
    int tid4 = lane & 3;
    int row0 = by * BM;
    int col0 = bx * BN;

    float ra[8], rb[8];
#pragma unroll
    for (int i = 0; i < 8; i++) {
        int idx = tid + i * 256;
        int gr = row0 + (idx >> 4), gk = idx & 15;
        ra[i] = (gr < M && gk < K) ? A[(size_t)gr * K + gk] : 0.f;
        int gn = col0 + (idx & 127), gkb = idx >> 7;
        rb[i] = (gkb < K && gn < Nn) ? W[(size_t)gkb * Nn + gn] : 0.f;
    }

    for (int k0 = 0; k0 < K; k0 += BK) {
#pragma unroll
        for (int i = 0; i < 8; i++) {
            int idx = tid + i * 256;
            int kkA = idx & 15, mA = idx >> 4;
            unsigned h = f2tf32(ra[i]);
            Ah[kkA][mA] = h;
            if (SPLIT) Al[kkA][mA] = f2tf32(ra[i] - __uint_as_float(h));
            int nB = idx & 127, kkB = idx >> 7;
            unsigned hb = f2tf32(rb[i]);
            Bh[kkB][nB] = hb;
            if (SPLIT) Bl[kkB][nB] = f2tf32(rb[i] - __uint_as_float(hb));
        }
        __syncthreads();

        int k1 = k0 + BK;
        if (k1 < K) {
#pragma unroll
            for (int i = 0; i < 8; i++) {
                int idx = tid + i * 256;
                int gr = row0 + (idx >> 4), gk = k1 + (idx & 15);
                ra[i] = (gr < M && gk < K) ? A[(size_t)gr * K + gk] : 0.f;
                int gn = col0 + (idx & 127), gkb = k1 + (idx >> 7);
                rb[i] = (gkb < K && gn < Nn) ? W[(size_t)gkb * Nn + gn] : 0.f;
            }
        }

#pragma unroll
        for (int ks = 0; ks < BK; ks += 8) {
            unsigned bh[4][2], bl[4][2];
#pragma unroll
            for (int nt = 0; nt < 4; nt++) {
                int cb = wn * 32 + nt * 8 + gid;
                bh[nt][0] = Bh[ks + tid4][cb];
                bh[nt][1] = Bh[ks + tid4 + 4][cb];
                if (SPLIT) {
                    bl[nt][0] = Bl[ks + tid4][cb];
                    bl[nt][1] = Bl[ks + tid4 + 4][cb];
                }
            }
#pragma unroll
            for (int mt = 0; mt < 4; mt++) {
                int rb0 = wm * 64 + mt * 16 + gid;
                unsigned ah0 = Ah[ks + tid4][rb0];
                unsigned ah1 = Ah[ks + tid4][rb0 + 8];
                unsigned ah2 = Ah[ks + tid4 + 4][rb0];
                unsigned ah3 = Ah[ks + tid4 + 4][rb0 + 8];
                unsigned al0 = 0, al1 = 0, al2 = 0, al3 = 0;
                if (SPLIT) {
                    al0 = Al[ks + tid4][rb0];
                    al1 = Al[ks + tid4][rb0 + 8];
                    al2 = Al[ks + tid4 + 4][rb0];
                    al3 = Al[ks + tid4 + 4][rb0 + 8];
                }
#pragma unroll
                for (int nt = 0; nt < 4; nt++) {
                    mma_tf32(c[mt][nt], ah0, ah1, ah2, ah3, bh[nt][0], bh[nt][1]);
                    if (SPLIT) {
                        mma_tf32(c[mt][nt], ah0, ah1, ah2, ah3, bl[nt][0], bl[nt][1]);
                        mma_tf32(c[mt][nt], al0, al1, al2, al3, bh[nt][0], bh[nt][1]);
                    }
                }
            }
        }
        __syncthreads();
    }
}

__global__ __launch_bounds__(256, 2) void gemm_bias_act(
    const float* __restrict__ A, const float* __restrict__ W,
    const float* __restrict__ bias, float* __restrict__ C,
    int M, int K, int Nn, int act)
{
    __shared__ unsigned Ah[BK][BM + 4];
    __shared__ unsigned Al[BK][BM + 4];
    __shared__ unsigned Bh[BK][BN + 4];
    __shared__ unsigned Bl[BK][BN + 4];
    float c[4][4][4];
#pragma unroll
    for (int a = 0; a < 4; a++)
#pragma unroll
        for (int b = 0; b < 4; b++)
#pragma unroll
            for (int d = 0; d < 4; d++) c[a][b][d] = 0.f;

    gemm_accum_mma<true>(A, W, M, K, Nn, blockIdx.x, blockIdx.y, c, Ah, Al, Bh, Bl);

    int tid = threadIdx.x, wid = tid >> 5, lane = tid & 31;
    int wm = wid & 1, wn = wid >> 1, gid = lane >> 2, tid4 = lane & 3;
    int row0 = blockIdx.y * BM, col0 = blockIdx.x * BN;
#pragma unroll
    for (int mt = 0; mt < 4; mt++) {
        int r0 = row0 + wm * 64 + mt * 16 + gid;
        int r1 = r0 + 8;
#pragma unroll
        for (int nt = 0; nt < 4; nt++) {
            int cb = col0 + wn * 32 + nt * 8 + tid4 * 2;
#pragma unroll
            for (int j = 0; j < 2; j++) {
                int gn = cb + j;
                if (gn >= Nn) continue;
                float b = bias[gn];
                if (r0 < M) {
                    float v = c[mt][nt][j] + b;
                    C[(size_t)r0 * Nn + gn] = act ? leaky(v) : v;
                }
                if (r1 < M) {
                    float v = c[mt][nt][2 + j] + b;
                    C[(size_t)r1 * Nn + gn] = act ? leaky(v) : v;
                }
            }
        }
    }
}

// Fused 4-way projection: z selects {q,k,v,skip}
__global__ __launch_bounds__(256, 2) void gemm_qkvs(
    const float* __restrict__ A,
    const float* __restrict__ W0, const float* __restrict__ b0, float* __restrict__ C0,
    const float* __restrict__ W1, const float* __restrict__ b1, float* __restrict__ C1,
    const float* __restrict__ W2, const float* __restrict__ b2, float* __restrict__ C2,
    const float* __restrict__ W3, const float* __restrict__ b3, float* __restrict__ C3)
{
    const float* W; const float* bia; float* C;
    switch (blockIdx.z) {
        case 0: W = W0; bia = b0; C = C0; break;
        case 1: W = W1; bia = b1; C = C1; break;
        case 2: W = W2; bia = b2; C = C2; break;
        default: W = W3; bia = b3; C = C3; break;
    }
    __shared__ unsigned Ah[BK][BM + 4];
    __shared__ unsigned Al[BK][BM + 4];
    __shared__ unsigned Bh[BK][BN + 4];
    __shared__ unsigned Bl[BK][BN + 4];
    float c[4][4][4];
#pragma unroll
    for (int a = 0; a < 4; a++)
#pragma unroll
        for (int b = 0; b < 4; b++)
#pragma unroll
            for (int d = 0; d < 4; d++) c[a][b][d] = 0.f;

    gemm_accum_mma<true>(A, W, NN, HC, HC, blockIdx.x, blockIdx.y, c, Ah, Al, Bh, Bl);

    int tid = threadIdx.x, wid = tid >> 5, lane = tid & 31;
    int wm = wid & 1, wn = wid >> 1, gid = lane >> 2, tid4 = lane & 3;
    int row0 = blockIdx.y * BM, col0 = blockIdx.x * BN;
#pragma unroll
    for (int mt = 0; mt < 4; mt++) {
        int r0 = row0 + wm * 64 + mt * 16 + gid;
        int r1 = r0 + 8;
#pragma unroll
        for (int nt = 0; nt < 4; nt++) {
            int cb = col0 + wn * 32 + nt * 8 + tid4 * 2;
            float bb0 = bia[cb], bb1 = bia[cb + 1];
            if (r0 < NN) {
                float2 v = make_float2(c[mt][nt][0] + bb0, c[mt][nt][1] + bb1);
                *(float2*)&C[(size_t)r0 * HC + cb] = v;
            }
            if (r1 < NN) {
                float2 v = make_float2(c[mt][nt][2] + bb0, c[mt][nt][3] + bb1);
                *(float2*)&C[(size_t)r1 * HC + cb] = v;
            }
        }
    }
}

// Fused tail: out[r] += sum_n leaky(r1[r,:]@Wrm[:,n] + brm[n]) * Wre[n]
// Single-pass tf32 (one-shot GEMM at the output; error ~3.5e-4, inside 1e-3 gate)
__global__ __launch_bounds__(256, 2) void gemm_head_tail(
    const float* __restrict__ A, const float* __restrict__ W,
    const float* __restrict__ bias, const float* __restrict__ wre,
    float* __restrict__ out)
{
    __shared__ unsigned Ah[BK][BM + 4];
    __shared__ unsigned Bh[BK][BN + 4];
    float c[4][4][4];
#pragma unroll
    for (int a = 0; a < 4; a++)
#pragma unroll
        for (int b = 0; b < 4; b++)
#pragma unroll
            for (int d = 0; d < 4; d++) c[a][b][d] = 0.f;

    gemm_accum_mma<false>(A, W, NN, RH, RH, blockIdx.x, blockIdx.y, c, Ah, Ah, Bh, Bh);

    int tid = threadIdx.x, wid = tid >> 5, lane = tid & 31;
    int wm = wid & 1, wn = wid >> 1, gid = lane >> 2, tid4 = lane & 3;
    int row0 = blockIdx.y * BM, col0 = blockIdx.x * BN;

    float bi[4][2], wr[4][2];
#pragma unroll
    for (int nt = 0; nt < 4; nt++)
#pragma unroll
        for (int j = 0; j < 2; j++) {
            int gn = col0 + wn * 32 + nt * 8 + tid4 * 2 + j;
            bi[nt][j] = (gn < RH) ? __ldg(bias + gn) : 0.f;
            wr[nt][j] = (gn < RH) ? __ldg(wre + gn)  : 0.f;
        }

#pragma unroll
    for (int mt = 0; mt < 4; mt++) {
        int r0 = row0 + wm * 64 + mt * 16 + gid;
        int r1 = r0 + 8;
        float p0 = 0.f, p1 = 0.f;
#pragma unroll
        for (int nt = 0; nt < 4; nt++)
#pragma unroll
            for (int j = 0; j < 2; j++) {
                p0 = fmaf(leaky(c[mt][nt][j]     + bi[nt][j]), wr[nt][j], p0);
                p1 = fmaf(leaky(c[mt][nt][2 + j] + bi[nt][j]), wr[nt][j], p1);
            }
        p0 += __shfl_xor_sync(0xffffffffu, p0, 1);
        p0 += __shfl_xor_sync(0xffffffffu, p0, 2);
        p1 += __shfl_xor_sync(0xffffffffu, p1, 1);
        p1 += __shfl_xor_sync(0xffffffffu, p1, 2);
        if (tid4 == 0) {
            if (r0 < NN) atomicAdd(out + r0, p0);
            if (r1 < NN) atomicAdd(out + r1, p1);
        }
    }
}

__global__ void out_init(const float* __restrict__ bre, float* __restrict__ out)
{
    int i = blockIdx.x * blockDim.x + threadIdx.x;
    if (i < NN) out[i] = __ldg(bre);
}

// ================= layer-1 projections (K = 2) =================
__global__ void proj_first(const float* __restrict__ x,
    const float* __restrict__ Wq, const float* __restrict__ bq,
    const float* __restrict__ Wk, const float* __restrict__ bk,
    const float* __restrict__ Wv, const float* __restrict__ bv,
    const float* __restrict__ Ws, const float* __restrict__ bs)
{
    int idx = blockIdx.x * blockDim.x + threadIdx.x;
    if (idx >= NN * HC) return;
    int n = idx >> 7, c = idx & 127;
    float x0 = x[n * 2], x1 = x[n * 2 + 1];
    g_q[idx]    = fmaf(x0, __ldg(Wq + c), fmaf(x1, __ldg(Wq + HC + c), __ldg(bq + c)));
    g_k[idx]    = fmaf(x0, __ldg(Wk + c), fmaf(x1, __ldg(Wk + HC + c), __ldg(bk + c)));
    g_v[idx]    = fmaf(x0, __ldg(Wv + c), fmaf(x1, __ldg(Wv + HC + c), __ldg(bv + c)));
    g_skip[idx] = fmaf(x0, __ldg(Ws + c), fmaf(x1, __ldg(Ws + HC + c), __ldg(bs + c)));
}

// ============ t = per-(node,head) projection of q through We/be ============
__global__ void t_compute(const float* __restrict__ We, const float* __restrict__ be)
{
    int idx = blockIdx.x * blockDim.x + threadIdx.x;   // n*64 + h*8 + f
    if (idx >= NN * 64) return;
    int f = idx & 7;
    int h = (idx >> 3) & 7;
    int n = idx >> 6;
    const float* w = (f < 7) ? (We + f * HC + h * 16) : (be + h * 16);
    const float* q = g_q + (size_t)n * HC + h * 16;
    float s = 0.f;
#pragma unroll
    for (int c = 0; c < 16; c++) s = fmaf(q[c], __ldg(w + c), s);
    g_t[idx] = s;
}

// ============ fused edge pass: 1 warp/node, float4 per lane ============
__global__ __launch_bounds__(256) void fused_aggregate(
    const float* __restrict__ We, const float* __restrict__ be)
{
    int node = (int)((blockIdx.x * (size_t)blockDim.x + threadIdx.x) >> 5);
    int lane = threadIdx.x & 31;
    if (node >= NN) return;
    int c0 = lane * 4;
    int h  = lane >> 2;

    float4 q4 = *(const float4*)(g_q + (size_t)node * HC + c0);
    const float* tp = g_t + (size_t)node * 64 + h * 8;
    float t0 = tp[0], t1 = tp[1], t2 = tp[2], t3 = tp[3];
    float t4 = tp[4], t5 = tp[5], t6 = tp[6], t7 = tp[7];

    int beg = g_rowptr[node], end = g_rowptr[node + 1];

    float m = __int_as_float(0xff800000);
    float a0 = 0.f, a1 = 0.f, a2 = 0.f, a3 = 0.f;
    float s0 = 0.f, s1 = 0.f, s2 = 0.f, s3 = 0.f;
    float s4 = 0.f, s5 = 0.f, s6 = 0.f, s7 = 0.f;   // s7 = den (ea[7]==1)

    for (int i = beg; i < end; i++) {
        int src = g_src_s[i];
        float4 k4 = *(const float4*)(g_k + (size_t)src * HC + c0);
        float4 v4 = *(const float4*)(g_v + (size_t)src * HC + c0);
        float4 ea0 = *(const float4*)(g_ea_s + (size_t)i * 8);
        float4 ea1 = *(const float4*)(g_ea_s + (size_t)i * 8 + 4);

        float p = q4.x * k4.x + q4.y * k4.y + q4.z * k4.z + q4.w * k4.w;
        p += __shfl_xor_sync(0xffffffffu, p, 1);
        p += __shfl_xor_sync(0xffffffffu, p, 2);

        float s = p;
        s = fmaf(ea0.x, t0, s);
        s = fmaf(ea0.y, t1, s);
        s = fmaf(ea0.z, t2, s);
        s = fmaf(ea0.w, t3, s);
        s = fmaf(ea1.x, t4, s);
        s = fmaf(ea1.y, t5, s);
        s = fmaf(ea1.z, t6, s);
        s = fmaf(ea1.w, t7, s);
        s *= 0.25f;                     // 1/sqrt(16)

        float mn = fmaxf(m, s);
        float corr = __expf(m - mn);
        float ex = __expf(s - mn);
        a0 = fmaf(a0, corr, ex * v4.x);
        a1 = fmaf(a1, corr, ex * v4.y);
        a2 = fmaf(a2, corr, ex * v4.z);
        a3 = fmaf(a3, corr, ex * v4.w);
        s0 = fmaf(s0, corr, ex * ea0.x);
        s1 = fmaf(s1, corr, ex * ea0.y);
        s2 = fmaf(s2, corr, ex * ea0.z);
        s3 = fmaf(s3, corr, ex * ea0.w);
        s4 = fmaf(s4, corr, ex * ea1.x);
        s5 = fmaf(s5, corr, ex * ea1.y);
        s6 = fmaf(s6, corr, ex * ea1.z);
        s7 = fmaf(s7, corr, ex);
        m = mn;
    }

    float den = s7;
    float inv = (den > 0.f) ? 1.f / den : 0.f;

    float4 sk = *(const float4*)(g_skip + (size_t)node * HC + c0);
    float r[4] = {a0, a1, a2, a3};
    float skv[4] = {sk.x, sk.y, sk.z, sk.w};
    float4 outv;
    float* op = (float*)&outv;
#pragma unroll
    for (int j = 0; j < 4; j++) {
        int c = c0 + j;
        float agg = r[j];
        agg = fmaf(s0, __ldg(We + 0 * HC + c), agg);
        agg = fmaf(s1, __ldg(We + 1 * HC + c), agg);
        agg = fmaf(s2, __ldg(We + 2 * HC + c), agg);
        agg = fmaf(s3, __ldg(We + 3 * HC + c), agg);
        agg = fmaf(s4, __ldg(We + 4 * HC + c), agg);
        agg = fmaf(s5, __ldg(We + 5 * HC + c), agg);
        agg = fmaf(s6, __ldg(We + 6 * HC + c), agg);
        agg = fmaf(s7, __ldg(be + c),          agg);
        op[j] = leaky(skv[j] + agg * inv);
    }
    *(float4*)(g_h + (size_t)node * HC + c0) = outv;
}

// ================= host orchestration =================
extern "C" void kernel_launch(void* const* d_in, const int* in_sizes, int n_in,
                              void* d_out, int out_size)
{
    const float* x   = (const float*)d_in[0];
    const int*   ei  = (const int*)  d_in[1];
    const float* ea  = (const float*)d_in[2];
    const float* Wq1 = (const float*)d_in[3];
    const float* bq1 = (const float*)d_in[4];
    const float* Wk1 = (const float*)d_in[5];
    const float* bk1 = (const float*)d_in[6];
    const float* Wv1 = (const float*)d_in[7];
    const float* bv1 = (const float*)d_in[8];
    const float* We1 = (const float*)d_in[9];
    const float* be1 = (const float*)d_in[10];
    const float* Ws1 = (const float*)d_in[11];
    const float* bs1 = (const float*)d_in[12];
    const float* Wqr = (const float*)d_in[13];
    const float* bqr = (const float*)d_in[14];
    const float* Wkr = (const float*)d_in[15];
    const float* bkr = (const float*)d_in[16];
    const float* Wvr = (const float*)d_in[17];
    const float* bvr = (const float*)d_in[18];
    const float* Wer = (const float*)d_in[19];
    const float* ber = (const float*)d_in[20];
    const float* Wsr = (const float*)d_in[21];
    const float* bsr = (const float*)d_in[22];
    const float* Wr1 = (const float*)d_in[23];
    const float* br1 = (const float*)d_in[24];
    const float* Wrm = (const float*)d_in[25];
    const float* brm = (const float*)d_in[26];
    const float* Wre = (const float*)d_in[27];
    const float* bre = (const float*)d_in[28];
    float* out = (float*)d_out;

    float *pq, *pk, *pv, *pskip, *ph, *pr1;
    cudaGetSymbolAddress((void**)&pq,    g_q);
    cudaGetSymbolAddress((void**)&pk,    g_k);
    cudaGetSymbolAddress((void**)&pv,    g_v);
    cudaGetSymbolAddress((void**)&pskip, g_skip);
    cudaGetSymbolAddress((void**)&ph,    g_h);
    cudaGetSymbolAddress((void**)&pr1,   g_r1);

    const int nodeBlocks  = (NN * HC + 255) / 256;
    const int edgeBlocks  = (EE + 255) / 256;
    const int aggBlocks   = (int)(((size_t)NN * 32 + 255) / 256);
    const int tBlocks     = (NN * 64 + 255) / 256;

    // ---- CSR build (once; reused by all 4 layers) ----
    csr_zero<<<(NN + 255) / 256, 256>>>();
    csr_hist<<<edgeBlocks, 256>>>(ei);
    csr_scan1<<<NBLK, SCAN_B>>>();
    csr_scan2<<<1, 32>>>();
    csr_scan3<<<(NN + 255) / 256, 256>>>();
    csr_scatter<<<edgeBlocks, 256>>>(ei, ea);

    // ---- layer 1 (input dim = 2) ----
    proj_first<<<nodeBlocks, 256>>>(x, Wq1, bq1, Wk1, bk1, Wv1, bv1, Ws1, bs1);
    t_compute<<<tBlocks, 256>>>(We1, be1);
    fused_aggregate<<<aggBlocks, 256>>>(We1, be1);

    // ---- layers 2..4 (input dim = 128), 3xTF32 tensor-core GEMMs ----
    dim3 gQKV(1, (NN + BM - 1) / BM, 4);
    for (int i = 0; i < 3; i++) {
        const float* Wq = Wqr + (size_t)i * HC * HC;    const float* bq = bqr + i * HC;
        const float* Wk = Wkr + (size_t)i * HC * HC;    const float* bk = bkr + i * HC;
        const float* Wv = Wvr + (size_t)i * HC * HC;    const float* bv = bvr + i * HC;
        const float* We = Wer + (size_t)i * FEdim * HC; const float* be = ber + i * HC;
        const float* Ws = Wsr + (size_t)i * HC * HC;    const float* bs = bsr + i * HC;

        gemm_qkvs<<<gQKV, 256>>>(ph, Wq, bq, pq, Wk, bk, pk, Wv, bv, pv, Ws, bs, pskip);
        t_compute<<<tBlocks, 256>>>(We, be);
        fused_aggregate<<<aggBlocks, 256>>>(We, be);
    }

    // ---- regression head: head1 3xTF32, tail 1xTF32 ----
    dim3 gH1((RH + BN - 1) / BN, (NN + BM - 1) / BM);
    gemm_bias_act<<<gH1, 256>>>(ph, Wr1, br1, pr1, NN, HC, RH, 1);
    out_init<<<(NN + 255) / 256, 256>>>(bre, out);
    gemm_head_tail<<<gH1, 256>>>(pr1, Wrm, brm, Wre, out);
}